// round 10
// baseline (speedup 1.0000x reference)
#include <cuda_runtime.h>
#include <cuda_fp16.h>
#include <cstdint>
#include <math.h>

// ---------------- problem constants ------------------------------------------
#define BATCH   2
#define LQ      15000
#define ROWS    (BATCH * LQ)      // 30000
#define CDIM    256
#define HEADS   8
#define HDIM    32
#define NPTS    4
#define HL      100
#define WL      150
#define LS      (HL * WL)

// ---------------- scratch ----------------------------------------------------
__device__ __align__(16) float   g_buf0[ROWS * CDIM];
__device__ __align__(16) float   g_buf2[ROWS * CDIM];
__device__ __align__(16) float   g_oa  [ROWS * 128];
__device__ __align__(16) __half  g_sf16[ROWS * CDIM];          // fp16 activations
__device__ __align__(16) __half  g_wt_h16[4 * 65536];          // [w][n][k]: dsa,val,comb,ff
__device__ __align__(16) __half  g_woa_h16[128 * 256];
__device__ __align__(16) float   g_boa[128];
__device__ __align__(16) float   g_wcomb[65536];               // W_out @ W_csa (fp32)
__device__ __align__(16) float   g_bcomb[256];

// ---------------- ptx helpers ------------------------------------------------
__device__ __forceinline__ uint32_t smem_u32(const void* p) {
    uint32_t a;
    asm("{ .reg .u64 t; cvta.to.shared.u64 t, %1; cvt.u32.u64 %0, t; }" : "=r"(a) : "l"(p));
    return a;
}
__device__ __forceinline__ void cpa16(uint32_t dst, const void* src, uint32_t sz) {
    asm volatile("cp.async.cg.shared.global [%0], [%1], 16, %2;"
                 :: "r"(dst), "l"(src), "r"(sz));
}
__device__ __forceinline__ void ldm_x4(uint32_t* r, uint32_t addr) {
    asm volatile("ldmatrix.sync.aligned.m8n8.x4.shared.b16 {%0,%1,%2,%3}, [%4];"
                 : "=r"(r[0]), "=r"(r[1]), "=r"(r[2]), "=r"(r[3]) : "r"(addr));
}
__device__ __forceinline__ void mma_f16(float* d, const uint32_t* a, const uint32_t* b) {
    asm volatile("mma.sync.aligned.m16n8k16.row.col.f32.f16.f16.f32 "
        "{%0,%1,%2,%3}, {%4,%5,%6,%7}, {%8,%9}, {%0,%1,%2,%3};"
        : "+f"(d[0]), "+f"(d[1]), "+f"(d[2]), "+f"(d[3])
        : "r"(a[0]), "r"(a[1]), "r"(a[2]), "r"(a[3]), "r"(b[0]), "r"(b[1]));
}
__device__ __forceinline__ float gelu_f(float x) {
    return 0.5f * x * (1.f + erff(x * 0.70710678118654752f));
}

// ---------------- W_comb = W_out @ W_csa, b_comb = b_out @ W_csa + b_csa ------
__global__ void comb_kernel(const float* __restrict__ Wo, const float* __restrict__ Wc,
                            const float* __restrict__ bo, const float* __restrict__ bc)
{
    const int n = threadIdx.x;
    const int k = blockIdx.x;
    float s = 0.f;
#pragma unroll 8
    for (int j = 0; j < 256; j++) s = fmaf(Wo[k * 256 + j], Wc[j * 256 + n], s);
    g_wcomb[k * 256 + n] = s;
    if (k == 0) {
        float sb = 0.f;
#pragma unroll 8
        for (int j = 0; j < 256; j++) sb = fmaf(bo[j], Wc[j * 256 + n], sb);
        g_bcomb[n] = sb + bc[n];
    }
}

// ---------------- weight prep: transpose + fp16 -------------------------------
#define PREP_TOT (4 * 65536 + 128 * 256 + 128)
__global__ void prep_kernel(const float* __restrict__ Wd, const float* __restrict__ Wv,
                            const float* __restrict__ Wf, const float* __restrict__ Woff,
                            const float* __restrict__ Watt, const float* __restrict__ boff,
                            const float* __restrict__ batt)
{
    int idx = blockIdx.x * 256 + threadIdx.x;
    if (idx < 4 * 65536) {
        int w = idx >> 16, e = idx & 65535, n = e >> 8, k = e & 255;
        float v;
        if (w == 0)      v = Wd[k * 256 + n];
        else if (w == 1) v = Wv[k * 256 + n];
        else if (w == 2) v = g_wcomb[k * 256 + n];
        else             v = Wf[k * 256 + n];
        g_wt_h16[w * 65536 + n * 256 + k] = __float2half_rn(v);
    } else if (idx < 4 * 65536 + 128 * 256) {
        int e = idx - 4 * 65536, n = e >> 8, k = e & 255;
        float v = 0.f;
        if (n < 64)       v = Woff[k * 64 + n];
        else if (n < 96)  v = Watt[k * 32 + (n - 64)];
        g_woa_h16[n * 256 + k] = __float2half_rn(v);
    } else if (idx < PREP_TOT) {
        int j = idx - (4 * 65536 + 128 * 256);
        g_boa[j] = (j < 64) ? boff[j] : (j < 96 ? batt[j - 64] : 0.f);
    }
}

// ---------------- elementwise conversion kernels ------------------------------
__global__ void cvt_f16_kernel(const float* __restrict__ x, __half* __restrict__ o)
{
    int base = (blockIdx.x * 256 + threadIdx.x) * 8;
    if (base >= ROWS * CDIM) return;
    float4 v0 = *(const float4*)(x + base);
    float4 v1 = *(const float4*)(x + base + 4);
    union { __half h[8]; uint4 u; } p;
    p.h[0] = __float2half_rn(v0.x); p.h[1] = __float2half_rn(v0.y);
    p.h[2] = __float2half_rn(v0.z); p.h[3] = __float2half_rn(v0.w);
    p.h[4] = __float2half_rn(v1.x); p.h[5] = __float2half_rn(v1.y);
    p.h[6] = __float2half_rn(v1.z); p.h[7] = __float2half_rn(v1.w);
    *(uint4*)(o + base) = p.u;
}

__global__ void add_f16_kernel(const float* __restrict__ a, const float* __restrict__ b,
                               __half* __restrict__ o)
{
    int base = (blockIdx.x * 256 + threadIdx.x) * 8;
    if (base >= ROWS * CDIM) return;
    float4 a0 = *(const float4*)(a + base), a1 = *(const float4*)(a + base + 4);
    float4 b0 = *(const float4*)(b + base), b1 = *(const float4*)(b + base + 4);
    union { __half h[8]; uint4 u; } p;
    p.h[0] = __float2half_rn(a0.x + b0.x); p.h[1] = __float2half_rn(a0.y + b0.y);
    p.h[2] = __float2half_rn(a0.z + b0.z); p.h[3] = __float2half_rn(a0.w + b0.w);
    p.h[4] = __float2half_rn(a1.x + b1.x); p.h[5] = __float2half_rn(a1.y + b1.y);
    p.h[6] = __float2half_rn(a1.z + b1.z); p.h[7] = __float2half_rn(a1.w + b1.w);
    *(uint4*)(o + base) = p.u;
}

// ---------------- deformable sampling ----------------------------------------
__device__ __forceinline__ float fetch_v(const float* __restrict__ vbase, int x, int y)
{
    if (x < 0 || x >= WL || y < 0 || y >= HL) return 0.f;
    return vbase[(size_t)(y * WL + x) * CDIM];
}

__global__ void msda_kernel(const float* __restrict__ value, const float* __restrict__ oa,
                            const float* __restrict__ ref, __half* __restrict__ o)
{
    const int warp = blockIdx.x * (blockDim.x >> 5) + (threadIdx.x >> 5);
    const int lane = threadIdx.x & 31;
    if (warp >= ROWS * HEADS) return;
    const int hd = warp & 7;
    const int bq = warp >> 3;
    const int b  = bq / LQ;

    const float* oarow = oa + (size_t)bq * 128;
    float a0 = oarow[64 + hd * 4 + 0];
    float a1 = oarow[64 + hd * 4 + 1];
    float a2 = oarow[64 + hd * 4 + 2];
    float a3 = oarow[64 + hd * 4 + 3];
    float m  = fmaxf(fmaxf(a0, a1), fmaxf(a2, a3));
    float e0 = expf(a0 - m), e1 = expf(a1 - m), e2 = expf(a2 - m), e3 = expf(a3 - m);
    float inv = 1.f / (e0 + e1 + e2 + e3);
    float w[4] = {e0 * inv, e1 * inv, e2 * inv, e3 * inv};

    const float rx = ref[(size_t)bq * 2 + 0];
    const float ry = ref[(size_t)bq * 2 + 1];
    const float* vbase = value + (size_t)b * LS * CDIM + hd * HDIM + lane;

    float acc = 0.f;
#pragma unroll
    for (int p = 0; p < NPTS; p++) {
        float ox = oarow[hd * 8 + p * 2 + 0];
        float oy = oarow[hd * 8 + p * 2 + 1];
        float X = (rx + ox / (float)WL) * (float)WL - 0.5f;
        float Y = (ry + oy / (float)HL) * (float)HL - 0.5f;
        float x0f = floorf(X), y0f = floorf(Y);
        float lx = X - x0f, ly = Y - y0f;
        int x0 = (int)x0f, y0 = (int)y0f;
        float s00 = fetch_v(vbase, x0,     y0);
        float s10 = fetch_v(vbase, x0 + 1, y0);
        float s01 = fetch_v(vbase, x0,     y0 + 1);
        float s11 = fetch_v(vbase, x0 + 1, y0 + 1);
        float sv  = s00 * (1.f - lx) * (1.f - ly) + s10 * lx * (1.f - ly)
                  + s01 * (1.f - lx) * ly         + s11 * lx * ly;
        acc = fmaf(w[p], sv, acc);
    }
    o[(size_t)bq * CDIM + hd * HDIM + lane] = __float2half_rn(acc);
}

// ============ fused GEMM: BM=128, BN=256 (full rows), 8 warps =================
// C = A16 @ W^T + bias [+ gelu] [+ res] [-> LN]
// MODE 0: plain f32 out
// MODE 1: LN(gemm+bias)*g+b -> fp16 out          (dsa + nds-LN)
// MODE 2: LN(res + gemm+bias)*g+b -> f32 + fp16  (comb + n1-LN)
// MODE 3: LN(res + gelu(gemm+bias))*g+b -> f32   (ff + n3-LN)
// One CTA owns entire rows -> in-place fp16 A==outH is safe.
#define FSTAGE 30720
#define FSMEM  (2 * FSTAGE)

template<int MODE>
__global__ void __launch_bounds__(256, 1) fgemm_kernel(
    const __half* __restrict__ A, const __half* __restrict__ B,
    const float* __restrict__ bias,
    const float* __restrict__ gamma, const float* __restrict__ beta,
    const float* __restrict__ res,
    float* __restrict__ outF, __half* __restrict__ outH)
{
    extern __shared__ __align__(128) char smem[];
    const int tid = threadIdx.x, lane = tid & 31, wid = tid >> 5;
    const int row0 = blockIdx.x * 128;
    const int wm = wid >> 2, wn = wid & 3;           // 2(M) x 4(N) warp grid
    const uint32_t sbase = smem_u32(smem);

    float acc[4][8][4];
#pragma unroll
    for (int i = 0; i < 4; i++)
#pragma unroll
        for (int j = 0; j < 8; j++)
#pragma unroll
            for (int q = 0; q < 4; q++) acc[i][j][q] = 0.f;

    auto load_stage = [&](int c, int s) {
        const int kk = c * 32;
        const uint32_t st = sbase + s * FSTAGE;
        // A: 512 granules (128 rows x 4)
#pragma unroll
        for (int i = 0; i < 2; i++) {
            int g = i * 256 + tid;
            int r = g >> 2, cc = g & 3;
            int gr = row0 + r;
            uint32_t sz = (gr < ROWS) ? 16u : 0u;
            cpa16(st + (uint32_t)(r * 80 + cc * 16),
                  A + (size_t)gr * 256 + kk + cc * 8, sz);
        }
        // B: 1024 granules (256 rows x 4)
#pragma unroll
        for (int i = 0; i < 4; i++) {
            int g = i * 256 + tid;
            int r = g >> 2, cc = g & 3;
            cpa16(st + 10240 + (uint32_t)(r * 80 + cc * 16),
                  B + (size_t)r * 256 + kk + cc * 8, 16u);
        }
        asm volatile("cp.async.commit_group;" ::: "memory");
    };

    load_stage(0, 0);
    load_stage(1, 1);

#pragma unroll 1
    for (int c = 0; c < 8; c++) {
        if (c < 7) asm volatile("cp.async.wait_group 1;" ::: "memory");
        else       asm volatile("cp.async.wait_group 0;" ::: "memory");
        __syncthreads();

        const uint32_t st = sbase + (c & 1) * FSTAGE;
#pragma unroll
        for (int k16 = 0; k16 < 2; k16++) {
            uint32_t bh[8][2];
            {
                int br = wn * 64 + ((lane >> 4) << 3) + (lane & 7);
                int bc = k16 * 16 + ((lane >> 3) & 1) * 8;
#pragma unroll
                for (int p = 0; p < 4; p++) {
                    uint32_t bd = st + 10240 + (uint32_t)((br + p * 16) * 80 + bc * 2);
                    uint32_t t4[4];
                    ldm_x4(t4, bd);
                    bh[2 * p][0] = t4[0]; bh[2 * p][1] = t4[1];
                    bh[2 * p + 1][0] = t4[2]; bh[2 * p + 1][1] = t4[3];
                }
            }
            int ar = wm * 64 + (lane & 15);
            int ac = k16 * 16 + ((lane >> 4) << 3);
#pragma unroll
            for (int mi = 0; mi < 4; mi++) {
                uint32_t ah[4];
                ldm_x4(ah, st + (uint32_t)((ar + mi * 16) * 80 + ac * 2));
#pragma unroll
                for (int nj = 0; nj < 8; nj++)
                    mma_f16(acc[mi][nj], ah, bh[nj]);
            }
        }
        __syncthreads();
        if (c <= 5) load_stage(c + 2, c & 1);
    }

    // ---- epilogue: bias (+gelu) (+res) ----
#pragma unroll
    for (int mi = 0; mi < 4; mi++) {
        int rl = wm * 64 + mi * 16 + (lane >> 2);       // local rows
        int grl = row0 + rl, grh = grl + 8;
#pragma unroll
        for (int nj = 0; nj < 8; nj++) {
            int col = wn * 64 + nj * 8 + (lane & 3) * 2;
            float b0 = __ldg(&bias[col]), b1 = __ldg(&bias[col + 1]);
            acc[mi][nj][0] += b0; acc[mi][nj][1] += b1;
            acc[mi][nj][2] += b0; acc[mi][nj][3] += b1;
            if (MODE == 3) {
                acc[mi][nj][0] = gelu_f(acc[mi][nj][0]);
                acc[mi][nj][1] = gelu_f(acc[mi][nj][1]);
                acc[mi][nj][2] = gelu_f(acc[mi][nj][2]);
                acc[mi][nj][3] = gelu_f(acc[mi][nj][3]);
            }
            if (MODE >= 2) {
                if (grl < ROWS) {
                    float2 r2 = *(const float2*)(res + (size_t)grl * 256 + col);
                    acc[mi][nj][0] += r2.x; acc[mi][nj][1] += r2.y;
                }
                if (grh < ROWS) {
                    float2 r2 = *(const float2*)(res + (size_t)grh * 256 + col);
                    acc[mi][nj][2] += r2.x; acc[mi][nj][3] += r2.y;
                }
            }
        }
    }

    if (MODE == 0) {
#pragma unroll
        for (int mi = 0; mi < 4; mi++) {
            int grl = row0 + wm * 64 + mi * 16 + (lane >> 2), grh = grl + 8;
#pragma unroll
            for (int nj = 0; nj < 8; nj++) {
                int col = wn * 64 + nj * 8 + (lane & 3) * 2;
                if (grl < ROWS) *(float2*)(outF + (size_t)grl * 256 + col) =
                    make_float2(acc[mi][nj][0], acc[mi][nj][1]);
                if (grh < ROWS) *(float2*)(outF + (size_t)grh * 256 + col) =
                    make_float2(acc[mi][nj][2], acc[mi][nj][3]);
            }
        }
        return;
    }

    // ---- row LayerNorm across the CTA's 256 columns ----
    float* s_sum = (float*)smem;          // [128][4]
    float* s_sq  = s_sum + 512;
    // (warps all passed the final __syncthreads of the main loop)
#pragma unroll
    for (int mi = 0; mi < 4; mi++) {
        float sl = 0.f, ql = 0.f, sh_ = 0.f, qh = 0.f;
#pragma unroll
        for (int nj = 0; nj < 8; nj++) {
            sl  += acc[mi][nj][0] + acc[mi][nj][1];
            ql  += acc[mi][nj][0] * acc[mi][nj][0] + acc[mi][nj][1] * acc[mi][nj][1];
            sh_ += acc[mi][nj][2] + acc[mi][nj][3];
            qh  += acc[mi][nj][2] * acc[mi][nj][2] + acc[mi][nj][3] * acc[mi][nj][3];
        }
#pragma unroll
        for (int d = 1; d <= 2; d <<= 1) {
            sl  += __shfl_xor_sync(0xffffffffu, sl,  d);
            ql  += __shfl_xor_sync(0xffffffffu, ql,  d);
            sh_ += __shfl_xor_sync(0xffffffffu, sh_, d);
            qh  += __shfl_xor_sync(0xffffffffu, qh,  d);
        }
        if ((lane & 3) == 0) {
            int rl = wm * 64 + mi * 16 + (lane >> 2);
            s_sum[rl * 4 + wn] = sl;       s_sq[rl * 4 + wn] = ql;
            s_sum[(rl + 8) * 4 + wn] = sh_; s_sq[(rl + 8) * 4 + wn] = qh;
        }
    }
    __syncthreads();

#pragma unroll
    for (int mi = 0; mi < 4; mi++) {
        int rl = wm * 64 + mi * 16 + (lane >> 2), rh = rl + 8;
        float ms_l = s_sum[rl * 4] + s_sum[rl * 4 + 1] + s_sum[rl * 4 + 2] + s_sum[rl * 4 + 3];
        float mq_l = s_sq[rl * 4] + s_sq[rl * 4 + 1] + s_sq[rl * 4 + 2] + s_sq[rl * 4 + 3];
        float ms_h = s_sum[rh * 4] + s_sum[rh * 4 + 1] + s_sum[rh * 4 + 2] + s_sum[rh * 4 + 3];
        float mq_h = s_sq[rh * 4] + s_sq[rh * 4 + 1] + s_sq[rh * 4 + 2] + s_sq[rh * 4 + 3];
        float mean_l = ms_l * (1.f / 256), mean_h = ms_h * (1.f / 256);
        float rs_l = rsqrtf(mq_l * (1.f / 256) - mean_l * mean_l + 1e-5f);
        float rs_h = rsqrtf(mq_h * (1.f / 256) - mean_h * mean_h + 1e-5f);
        int grl = row0 + rl, grh = row0 + rh;
#pragma unroll
        for (int nj = 0; nj < 8; nj++) {
            int col = wn * 64 + nj * 8 + (lane & 3) * 2;
            float g0 = __ldg(&gamma[col]), g1 = __ldg(&gamma[col + 1]);
            float e0 = __ldg(&beta[col]),  e1 = __ldg(&beta[col + 1]);
            float y0 = (acc[mi][nj][0] - mean_l) * rs_l * g0 + e0;
            float y1 = (acc[mi][nj][1] - mean_l) * rs_l * g1 + e1;
            float y2 = (acc[mi][nj][2] - mean_h) * rs_h * g0 + e0;
            float y3 = (acc[mi][nj][3] - mean_h) * rs_h * g1 + e1;
            if (MODE == 2 || MODE == 3) {
                if (grl < ROWS) *(float2*)(outF + (size_t)grl * 256 + col) = make_float2(y0, y1);
                if (grh < ROWS) *(float2*)(outF + (size_t)grh * 256 + col) = make_float2(y2, y3);
            }
            if (MODE == 1 || MODE == 2) {
                union { __half h[2]; uint32_t u; } pl, ph;
                pl.h[0] = __float2half_rn(y0); pl.h[1] = __float2half_rn(y1);
                ph.h[0] = __float2half_rn(y2); ph.h[1] = __float2half_rn(y3);
                if (grl < ROWS) *(uint32_t*)(outH + (size_t)grl * 256 + col) = pl.u;
                if (grh < ROWS) *(uint32_t*)(outH + (size_t)grh * 256 + col) = ph.u;
            }
        }
    }
}

// ---------------- oa GEMM: BM=128 BN=128, 4 warps, 2 CTAs/SM (as R9) ----------
#define GSTAGE 20480
#define GSMEM  (2 * GSTAGE)

__global__ void __launch_bounds__(128, 2) oagemm_kernel(
    const __half* __restrict__ A, const __half* __restrict__ Bh,
    const float* __restrict__ bias, float* __restrict__ outF)
{
    extern __shared__ __align__(128) char smem[];
    const int tid = threadIdx.x, lane = tid & 31, wid = tid >> 5;
    const int row0 = blockIdx.x * 128;
    const int wm = wid >> 1, wn = wid & 1;
    const uint32_t sbase = smem_u32(smem);

    float acc[4][8][4];
#pragma unroll
    for (int i = 0; i < 4; i++)
#pragma unroll
        for (int j = 0; j < 8; j++)
#pragma unroll
            for (int q = 0; q < 4; q++) acc[i][j][q] = 0.f;

    auto load_stage = [&](int c, int s) {
        const int kk = c * 32;
        const uint32_t st = sbase + s * GSTAGE;
#pragma unroll
        for (int i = 0; i < 4; i++) {
            int g = i * 128 + tid;
            int r = g >> 2, cc = g & 3;
            uint32_t so = (uint32_t)(r * 80 + cc * 16);
            int gr = row0 + r;
            uint32_t sz = (gr < ROWS) ? 16u : 0u;
            cpa16(st + so,         A  + (size_t)gr * 256 + kk + cc * 8, sz);
            cpa16(st + 10240 + so, Bh + (size_t)r * 256 + kk + cc * 8, 16u);
        }
        asm volatile("cp.async.commit_group;" ::: "memory");
    };

    load_stage(0, 0);
    load_stage(1, 1);

#pragma unroll 1
    for (int c = 0; c < 8; c++) {
        if (c < 7) asm volatile("cp.async.wait_group 1;" ::: "memory");
        else       asm volatile("cp.async.wait_group 0;" ::: "memory");
        __syncthreads();

        const uint32_t st = sbase + (c & 1) * GSTAGE;
#pragma unroll
        for (int k16 = 0; k16 < 2; k16++) {
            uint32_t bh[8][2];
            {
                int br = wn * 64 + ((lane >> 4) << 3) + (lane & 7);
                int bc = k16 * 16 + ((lane >> 3) & 1) * 8;
#pragma unroll
                for (int p = 0; p < 4; p++) {
                    uint32_t bd = st + 10240 + (uint32_t)((br + p * 16) * 80 + bc * 2);
                    uint32_t t4[4];
                    ldm_x4(t4, bd);
                    bh[2 * p][0] = t4[0]; bh[2 * p][1] = t4[1];
                    bh[2 * p + 1][0] = t4[2]; bh[2 * p + 1][1] = t4[3];
                }
            }
            int ar = wm * 64 + (lane & 15);
            int ac = k16 * 16 + ((lane >> 4) << 3);
#pragma unroll
            for (int mi = 0; mi < 4; mi++) {
                uint32_t ah[4];
                ldm_x4(ah, st + (uint32_t)((ar + mi * 16) * 80 + ac * 2));
#pragma unroll
                for (int nj = 0; nj < 8; nj++)
                    mma_f16(acc[mi][nj], ah, bh[nj]);
            }
        }
        __syncthreads();
        if (c <= 5) load_stage(c + 2, c & 1);
    }

#pragma unroll
    for (int mi = 0; mi < 4; mi++) {
        int rl = row0 + wm * 64 + mi * 16 + (lane >> 2);
        int rh = rl + 8;
#pragma unroll
        for (int nj = 0; nj < 8; nj++) {
            int col = wn * 64 + nj * 8 + (lane & 3) * 2;
            float b0 = __ldg(&bias[col]), b1 = __ldg(&bias[col + 1]);
            if (rl < ROWS) *(float2*)(outF + (size_t)rl * 128 + col) =
                make_float2(acc[mi][nj][0] + b0, acc[mi][nj][1] + b1);
            if (rh < ROWS) *(float2*)(outF + (size_t)rh * 128 + col) =
                make_float2(acc[mi][nj][2] + b0, acc[mi][nj][3] + b1);
        }
    }
}

// ---------------- launch -------------------------------------------------------
extern "C" void kernel_launch(void* const* d_in, const int* in_sizes, int n_in,
                              void* d_out, int out_size)
{
    const float* tgt       = (const float*)d_in[0];
    const float* query_pos = (const float*)d_in[1];
    const float* refpts    = (const float*)d_in[4];
    const float* src       = (const float*)d_in[6];
    const float* W_dsa = (const float*)d_in[10]; const float* b_dsa = (const float*)d_in[11];
    const float* g_nds = (const float*)d_in[12]; const float* b_nds = (const float*)d_in[13];
    const float* W_off = (const float*)d_in[14]; const float* b_off = (const float*)d_in[15];
    const float* W_att = (const float*)d_in[16]; const float* b_att = (const float*)d_in[17];
    const float* W_val = (const float*)d_in[18]; const float* b_val = (const float*)d_in[19];
    const float* W_out = (const float*)d_in[20]; const float* b_out = (const float*)d_in[21];
    const float* W_csa = (const float*)d_in[22]; const float* b_csa = (const float*)d_in[23];
    const float* g_n1  = (const float*)d_in[24]; const float* b_n1  = (const float*)d_in[25];
    const float* W_ff  = (const float*)d_in[26]; const float* b_ff  = (const float*)d_in[27];
    const float* g_n3  = (const float*)d_in[28]; const float* b_n3  = (const float*)d_in[29];
    float* out = (float*)d_out;

    float *buf0, *buf2, *oa, *boa, *bcomb;
    __half *sf16, *wth, *woah;
    cudaGetSymbolAddress((void**)&buf0,  g_buf0);
    cudaGetSymbolAddress((void**)&buf2,  g_buf2);
    cudaGetSymbolAddress((void**)&oa,    g_oa);
    cudaGetSymbolAddress((void**)&boa,   g_boa);
    cudaGetSymbolAddress((void**)&bcomb, g_bcomb);
    cudaGetSymbolAddress((void**)&sf16,  g_sf16);
    cudaGetSymbolAddress((void**)&wth,   g_wt_h16);
    cudaGetSymbolAddress((void**)&woah,  g_woa_h16);

    cudaFuncSetAttribute((const void*)fgemm_kernel<0>,
                         cudaFuncAttributeMaxDynamicSharedMemorySize, FSMEM);
    cudaFuncSetAttribute((const void*)fgemm_kernel<1>,
                         cudaFuncAttributeMaxDynamicSharedMemorySize, FSMEM);
    cudaFuncSetAttribute((const void*)fgemm_kernel<2>,
                         cudaFuncAttributeMaxDynamicSharedMemorySize, FSMEM);
    cudaFuncSetAttribute((const void*)fgemm_kernel<3>,
                         cudaFuncAttributeMaxDynamicSharedMemorySize, FSMEM);
    cudaFuncSetAttribute((const void*)oagemm_kernel,
                         cudaFuncAttributeMaxDynamicSharedMemorySize, GSMEM);

    const int MT  = (ROWS + 127) / 128;       // 235 row tiles
    const int EW8 = (ROWS * CDIM / 8 + 255) / 256;

    // 0) combined weight + prep
    comb_kernel<<<256, 256>>>(W_out, W_csa, b_out, b_csa);
    prep_kernel<<<(PREP_TOT + 255) / 256, 256>>>(W_dsa, W_val, W_ff,
                                                 W_off, W_att, b_off, b_att);
    // 1) src -> fp16
    cvt_f16_kernel<<<EW8, 256>>>(src, sf16);
    // 2) dsa GEMM + LN(nds) -> sf16 (in-place safe: CTA owns full rows)
    fgemm_kernel<1><<<MT, 256, FSMEM>>>(sf16, wth + 0 * 65536, b_dsa,
                                        g_nds, b_nds, nullptr, nullptr, sf16);
    // 3) value GEMM -> buf0 (f32)
    fgemm_kernel<0><<<MT, 256, FSMEM>>>(sf16, wth + 1 * 65536, b_val,
                                        nullptr, nullptr, nullptr, buf0, nullptr);
    // 4) q = tgt + query_pos -> fp16
    add_f16_kernel<<<EW8, 256>>>(tgt, query_pos, sf16);
    // 5) offsets+attention GEMM (N=128 padded) -> oa
    oagemm_kernel<<<MT, 128, GSMEM>>>(sf16, woah, boa, oa);
    // 6) deformable sampling -> fp16 (sf16)
    msda_kernel<<<(ROWS * HEADS + 7) / 8, 256>>>(buf0, oa, refpts, sf16);
    // 7) comb GEMM + residual(tgt) + LN(n1) -> buf2 (f32) + sf16
    fgemm_kernel<2><<<MT, 256, FSMEM>>>(sf16, wth + 2 * 65536, bcomb,
                                        g_n1, b_n1, tgt, buf2, sf16);
    // 8) ff GEMM + gelu + residual(buf2) + LN(n3) -> out
    fgemm_kernel<3><<<MT, 256, FSMEM>>>(sf16, wth + 3 * 65536, b_ff,
                                        g_n3, b_n3, buf2, out, nullptr);
}

// round 12
// speedup vs baseline: 1.0882x; 1.0882x over previous
#include <cuda_runtime.h>
#include <cuda_fp16.h>
#include <cstdint>
#include <math.h>

// ---------------- problem constants ------------------------------------------
#define BATCH   2
#define LQ      15000
#define ROWS    (BATCH * LQ)      // 30000
#define CDIM    256
#define HEADS   8
#define HDIM    32
#define NPTS    4
#define HL      100
#define WL      150
#define LS      (HL * WL)

// ---------------- scratch ----------------------------------------------------
__device__ __align__(16) float   g_buf0[ROWS * CDIM];
__device__ __align__(16) float   g_buf2[ROWS * CDIM];
__device__ __align__(16) float   g_oa  [ROWS * 128];
__device__ __align__(16) __half  g_sf16[ROWS * CDIM];          // fp16 activations
__device__ __align__(16) __half  g_wt_h16[4 * 65536];          // [w][n][k]: dsa,val,comb,ff
__device__ __align__(16) __half  g_woa_h16[128 * 256];
__device__ __align__(16) float   g_boa[128];
__device__ __align__(16) float   g_wcomb[65536];               // W_out @ W_csa (fp32)
__device__ __align__(16) float   g_bcomb[256];

// ---------------- ptx helpers ------------------------------------------------
__device__ __forceinline__ uint32_t smem_u32(const void* p) {
    uint32_t a;
    asm("{ .reg .u64 t; cvta.to.shared.u64 t, %1; cvt.u32.u64 %0, t; }" : "=r"(a) : "l"(p));
    return a;
}
__device__ __forceinline__ void cpa16(uint32_t dst, const void* src, uint32_t sz) {
    asm volatile("cp.async.cg.shared.global [%0], [%1], 16, %2;"
                 :: "r"(dst), "l"(src), "r"(sz));
}
__device__ __forceinline__ void ldm_x4(uint32_t* r, uint32_t addr) {
    asm volatile("ldmatrix.sync.aligned.m8n8.x4.shared.b16 {%0,%1,%2,%3}, [%4];"
                 : "=r"(r[0]), "=r"(r[1]), "=r"(r[2]), "=r"(r[3]) : "r"(addr));
}
__device__ __forceinline__ void mma_f16(float* d, const uint32_t* a, const uint32_t* b) {
    asm volatile("mma.sync.aligned.m16n8k16.row.col.f32.f16.f16.f32 "
        "{%0,%1,%2,%3}, {%4,%5,%6,%7}, {%8,%9}, {%0,%1,%2,%3};"
        : "+f"(d[0]), "+f"(d[1]), "+f"(d[2]), "+f"(d[3])
        : "r"(a[0]), "r"(a[1]), "r"(a[2]), "r"(a[3]), "r"(b[0]), "r"(b[1]));
}
__device__ __forceinline__ float gelu_f(float x) {
    return 0.5f * x * (1.f + erff(x * 0.70710678118654752f));
}

// ---------------- W_comb = W_out @ W_csa, b_comb = b_out @ W_csa + b_csa ------
__global__ void comb_kernel(const float* __restrict__ Wo, const float* __restrict__ Wc,
                            const float* __restrict__ bo, const float* __restrict__ bc)
{
    const int n = threadIdx.x;
    const int k = blockIdx.x;
    float s = 0.f;
#pragma unroll 8
    for (int j = 0; j < 256; j++) s = fmaf(Wo[k * 256 + j], Wc[j * 256 + n], s);
    g_wcomb[k * 256 + n] = s;
    if (k == 0) {
        float sb = 0.f;
#pragma unroll 8
        for (int j = 0; j < 256; j++) sb = fmaf(bo[j], Wc[j * 256 + n], sb);
        g_bcomb[n] = sb + bc[n];
    }
}

// ---------------- weight prep: transpose + fp16 -------------------------------
#define PREP_TOT (4 * 65536 + 128 * 256 + 128)
__global__ void prep_kernel(const float* __restrict__ Wd, const float* __restrict__ Wv,
                            const float* __restrict__ Wf, const float* __restrict__ Woff,
                            const float* __restrict__ Watt, const float* __restrict__ boff,
                            const float* __restrict__ batt)
{
    int idx = blockIdx.x * 256 + threadIdx.x;
    if (idx < 4 * 65536) {
        int w = idx >> 16, e = idx & 65535, n = e >> 8, k = e & 255;
        float v;
        if (w == 0)      v = Wd[k * 256 + n];
        else if (w == 1) v = Wv[k * 256 + n];
        else if (w == 2) v = g_wcomb[k * 256 + n];
        else             v = Wf[k * 256 + n];
        g_wt_h16[w * 65536 + n * 256 + k] = __float2half_rn(v);
    } else if (idx < 4 * 65536 + 128 * 256) {
        int e = idx - 4 * 65536, n = e >> 8, k = e & 255;
        float v = 0.f;
        if (n < 64)       v = Woff[k * 64 + n];
        else if (n < 96)  v = Watt[k * 32 + (n - 64)];
        g_woa_h16[n * 256 + k] = __float2half_rn(v);
    } else if (idx < PREP_TOT) {
        int j = idx - (4 * 65536 + 128 * 256);
        g_boa[j] = (j < 64) ? boff[j] : (j < 96 ? batt[j - 64] : 0.f);
    }
}

// ---------------- elementwise conversion kernels ------------------------------
__global__ void cvt_f16_kernel(const float* __restrict__ x, __half* __restrict__ o)
{
    int base = (blockIdx.x * 256 + threadIdx.x) * 8;
    if (base >= ROWS * CDIM) return;
    float4 v0 = *(const float4*)(x + base);
    float4 v1 = *(const float4*)(x + base + 4);
    union { __half h[8]; uint4 u; } p;
    p.h[0] = __float2half_rn(v0.x); p.h[1] = __float2half_rn(v0.y);
    p.h[2] = __float2half_rn(v0.z); p.h[3] = __float2half_rn(v0.w);
    p.h[4] = __float2half_rn(v1.x); p.h[5] = __float2half_rn(v1.y);
    p.h[6] = __float2half_rn(v1.z); p.h[7] = __float2half_rn(v1.w);
    *(uint4*)(o + base) = p.u;
}

__global__ void add_f16_kernel(const float* __restrict__ a, const float* __restrict__ b,
                               __half* __restrict__ o)
{
    int base = (blockIdx.x * 256 + threadIdx.x) * 8;
    if (base >= ROWS * CDIM) return;
    float4 a0 = *(const float4*)(a + base), a1 = *(const float4*)(a + base + 4);
    float4 b0 = *(const float4*)(b + base), b1 = *(const float4*)(b + base + 4);
    union { __half h[8]; uint4 u; } p;
    p.h[0] = __float2half_rn(a0.x + b0.x); p.h[1] = __float2half_rn(a0.y + b0.y);
    p.h[2] = __float2half_rn(a0.z + b0.z); p.h[3] = __float2half_rn(a0.w + b0.w);
    p.h[4] = __float2half_rn(a1.x + b1.x); p.h[5] = __float2half_rn(a1.y + b1.y);
    p.h[6] = __float2half_rn(a1.z + b1.z); p.h[7] = __float2half_rn(a1.w + b1.w);
    *(uint4*)(o + base) = p.u;
}

// ---------------- deformable sampling ----------------------------------------
__device__ __forceinline__ float fetch_v(const float* __restrict__ vbase, int x, int y)
{
    if (x < 0 || x >= WL || y < 0 || y >= HL) return 0.f;
    return vbase[(size_t)(y * WL + x) * CDIM];
}

__global__ void msda_kernel(const float* __restrict__ value, const float* __restrict__ oa,
                            const float* __restrict__ ref, __half* __restrict__ o)
{
    const int warp = blockIdx.x * (blockDim.x >> 5) + (threadIdx.x >> 5);
    const int lane = threadIdx.x & 31;
    if (warp >= ROWS * HEADS) return;
    const int hd = warp & 7;
    const int bq = warp >> 3;
    const int b  = bq / LQ;

    const float* oarow = oa + (size_t)bq * 128;
    float a0 = oarow[64 + hd * 4 + 0];
    float a1 = oarow[64 + hd * 4 + 1];
    float a2 = oarow[64 + hd * 4 + 2];
    float a3 = oarow[64 + hd * 4 + 3];
    float m  = fmaxf(fmaxf(a0, a1), fmaxf(a2, a3));
    float e0 = expf(a0 - m), e1 = expf(a1 - m), e2 = expf(a2 - m), e3 = expf(a3 - m);
    float inv = 1.f / (e0 + e1 + e2 + e3);
    float w[4] = {e0 * inv, e1 * inv, e2 * inv, e3 * inv};

    const float rx = ref[(size_t)bq * 2 + 0];
    const float ry = ref[(size_t)bq * 2 + 1];
    const float* vbase = value + (size_t)b * LS * CDIM + hd * HDIM + lane;

    float acc = 0.f;
#pragma unroll
    for (int p = 0; p < NPTS; p++) {
        float ox = oarow[hd * 8 + p * 2 + 0];
        float oy = oarow[hd * 8 + p * 2 + 1];
        float X = (rx + ox / (float)WL) * (float)WL - 0.5f;
        float Y = (ry + oy / (float)HL) * (float)HL - 0.5f;
        float x0f = floorf(X), y0f = floorf(Y);
        float lx = X - x0f, ly = Y - y0f;
        int x0 = (int)x0f, y0 = (int)y0f;
        float s00 = fetch_v(vbase, x0,     y0);
        float s10 = fetch_v(vbase, x0 + 1, y0);
        float s01 = fetch_v(vbase, x0,     y0 + 1);
        float s11 = fetch_v(vbase, x0 + 1, y0 + 1);
        float sv  = s00 * (1.f - lx) * (1.f - ly) + s10 * lx * (1.f - ly)
                  + s01 * (1.f - lx) * ly         + s11 * lx * ly;
        acc = fmaf(w[p], sv, acc);
    }
    o[(size_t)bq * CDIM + hd * HDIM + lane] = __float2half_rn(acc);
}

// ============ fused GEMM: BM=64, BN=256 (full rows), 8 warps, 2 CTAs/SM =======
// C = A16 @ W^T + bias [+ gelu] [+ res] [-> LN]
// MODE 0: plain f32 out
// MODE 1: LN(gemm+bias)*g+b -> fp16 out          (dsa + nds-LN)
// MODE 2: LN(res + gemm+bias)*g+b -> f32 + fp16  (comb + n1-LN)
// MODE 3: LN(res + gelu(gemm+bias))*g+b -> f32   (ff + n3-LN)
// Warp grid 2(M) x 4(N), warp tile 32x64. One CTA owns entire rows
// -> in-place fp16 A==outH is safe.
#define FSTAGE 25600              // A: 64*80, B: 256*80
#define FSMEM  (2 * FSTAGE)

template<int MODE>
__global__ void __launch_bounds__(256, 2) fgemm_kernel(
    const __half* __restrict__ A, const __half* __restrict__ B,
    const float* __restrict__ bias,
    const float* __restrict__ gamma, const float* __restrict__ beta,
    const float* __restrict__ res,
    float* __restrict__ outF, __half* __restrict__ outH)
{
    extern __shared__ __align__(128) char smem[];
    const int tid = threadIdx.x, lane = tid & 31, wid = tid >> 5;
    const int row0 = blockIdx.x * 64;
    const int wm = wid >> 2, wn = wid & 3;           // 2(M) x 4(N) warp grid
    const uint32_t sbase = smem_u32(smem);

    float acc[2][8][4];
#pragma unroll
    for (int i = 0; i < 2; i++)
#pragma unroll
        for (int j = 0; j < 8; j++)
#pragma unroll
            for (int q = 0; q < 4; q++) acc[i][j][q] = 0.f;

    auto load_stage = [&](int c, int s) {
        const int kk = c * 32;
        const uint32_t st = sbase + s * FSTAGE;
        // A: 256 granules (64 rows x 4)
        {
            int r = tid >> 2, cc = tid & 3;
            int gr = row0 + r;
            uint32_t sz = (gr < ROWS) ? 16u : 0u;
            cpa16(st + (uint32_t)(r * 80 + cc * 16),
                  A + (size_t)gr * 256 + kk + cc * 8, sz);
        }
        // B: 1024 granules (256 rows x 4)
#pragma unroll
        for (int i = 0; i < 4; i++) {
            int g = i * 256 + tid;
            int r = g >> 2, cc = g & 3;
            cpa16(st + 5120 + (uint32_t)(r * 80 + cc * 16),
                  B + (size_t)r * 256 + kk + cc * 8, 16u);
        }
        asm volatile("cp.async.commit_group;" ::: "memory");
    };

    load_stage(0, 0);
    load_stage(1, 1);

#pragma unroll 1
    for (int c = 0; c < 8; c++) {
        if (c < 7) asm volatile("cp.async.wait_group 1;" ::: "memory");
        else       asm volatile("cp.async.wait_group 0;" ::: "memory");
        __syncthreads();

        const uint32_t st = sbase + (c & 1) * FSTAGE;
#pragma unroll
        for (int k16 = 0; k16 < 2; k16++) {
            uint32_t bh[8][2];
            {
                int br = wn * 64 + ((lane >> 4) << 3) + (lane & 7);
                int bc = k16 * 16 + ((lane >> 3) & 1) * 8;
#pragma unroll
                for (int p = 0; p < 4; p++) {
                    uint32_t bd = st + 5120 + (uint32_t)((br + p * 16) * 80 + bc * 2);
                    uint32_t t4[4];
                    ldm_x4(t4, bd);
                    bh[2 * p][0] = t4[0]; bh[2 * p][1] = t4[1];
                    bh[2 * p + 1][0] = t4[2]; bh[2 * p + 1][1] = t4[3];
                }
            }
            int ar = wm * 32 + (lane & 15);
            int ac = k16 * 16 + ((lane >> 4) << 3);
#pragma unroll
            for (int mi = 0; mi < 2; mi++) {
                uint32_t ah[4];
                ldm_x4(ah, st + (uint32_t)((ar + mi * 16) * 80 + ac * 2));
#pragma unroll
                for (int nj = 0; nj < 8; nj++)
                    mma_f16(acc[mi][nj], ah, bh[nj]);
            }
        }
        __syncthreads();
        if (c <= 5) load_stage(c + 2, c & 1);
    }

    // ---- epilogue: bias (+gelu) (+res) ----
#pragma unroll
    for (int mi = 0; mi < 2; mi++) {
        int rl = wm * 32 + mi * 16 + (lane >> 2);       // local rows
        int grl = row0 + rl, grh = grl + 8;
#pragma unroll
        for (int nj = 0; nj < 8; nj++) {
            int col = wn * 64 + nj * 8 + (lane & 3) * 2;
            float b0 = __ldg(&bias[col]), b1 = __ldg(&bias[col + 1]);
            acc[mi][nj][0] += b0; acc[mi][nj][1] += b1;
            acc[mi][nj][2] += b0; acc[mi][nj][3] += b1;
            if (MODE == 3) {
                acc[mi][nj][0] = gelu_f(acc[mi][nj][0]);
                acc[mi][nj][1] = gelu_f(acc[mi][nj][1]);
                acc[mi][nj][2] = gelu_f(acc[mi][nj][2]);
                acc[mi][nj][3] = gelu_f(acc[mi][nj][3]);
            }
            if (MODE >= 2) {
                if (grl < ROWS) {
                    float2 r2 = *(const float2*)(res + (size_t)grl * 256 + col);
                    acc[mi][nj][0] += r2.x; acc[mi][nj][1] += r2.y;
                }
                if (grh < ROWS) {
                    float2 r2 = *(const float2*)(res + (size_t)grh * 256 + col);
                    acc[mi][nj][2] += r2.x; acc[mi][nj][3] += r2.y;
                }
            }
        }
    }

    if (MODE == 0) {
#pragma unroll
        for (int mi = 0; mi < 2; mi++) {
            int grl = row0 + wm * 32 + mi * 16 + (lane >> 2), grh = grl + 8;
#pragma unroll
            for (int nj = 0; nj < 8; nj++) {
                int col = wn * 64 + nj * 8 + (lane & 3) * 2;
                if (grl < ROWS) *(float2*)(outF + (size_t)grl * 256 + col) =
                    make_float2(acc[mi][nj][0], acc[mi][nj][1]);
                if (grh < ROWS) *(float2*)(outF + (size_t)grh * 256 + col) =
                    make_float2(acc[mi][nj][2], acc[mi][nj][3]);
            }
        }
        return;
    }

    // ---- row LayerNorm across the CTA's 256 columns ----
    float* s_sum = (float*)smem;          // [64][4]
    float* s_sq  = s_sum + 256;
#pragma unroll
    for (int mi = 0; mi < 2; mi++) {
        float sl = 0.f, ql = 0.f, sh_ = 0.f, qh = 0.f;
#pragma unroll
        for (int nj = 0; nj < 8; nj++) {
            sl  += acc[mi][nj][0] + acc[mi][nj][1];
            ql  += acc[mi][nj][0] * acc[mi][nj][0] + acc[mi][nj][1] * acc[mi][nj][1];
            sh_ += acc[mi][nj][2] + acc[mi][nj][3];
            qh  += acc[mi][nj][2] * acc[mi][nj][2] + acc[mi][nj][3] * acc[mi][nj][3];
        }
#pragma unroll
        for (int d = 1; d <= 2; d <<= 1) {
            sl  += __shfl_xor_sync(0xffffffffu, sl,  d);
            ql  += __shfl_xor_sync(0xffffffffu, ql,  d);
            sh_ += __shfl_xor_sync(0xffffffffu, sh_, d);
            qh  += __shfl_xor_sync(0xffffffffu, qh,  d);
        }
        if ((lane & 3) == 0) {
            int rl = wm * 32 + mi * 16 + (lane >> 2);
            s_sum[rl * 4 + wn] = sl;        s_sq[rl * 4 + wn] = ql;
            s_sum[(rl + 8) * 4 + wn] = sh_; s_sq[(rl + 8) * 4 + wn] = qh;
        }
    }
    __syncthreads();

#pragma unroll
    for (int mi = 0; mi < 2; mi++) {
        int rl = wm * 32 + mi * 16 + (lane >> 2), rh = rl + 8;
        float ms_l = s_sum[rl * 4] + s_sum[rl * 4 + 1] + s_sum[rl * 4 + 2] + s_sum[rl * 4 + 3];
        float mq_l = s_sq[rl * 4] + s_sq[rl * 4 + 1] + s_sq[rl * 4 + 2] + s_sq[rl * 4 + 3];
        float ms_h = s_sum[rh * 4] + s_sum[rh * 4 + 1] + s_sum[rh * 4 + 2] + s_sum[rh * 4 + 3];
        float mq_h = s_sq[rh * 4] + s_sq[rh * 4 + 1] + s_sq[rh * 4 + 2] + s_sq[rh * 4 + 3];
        float mean_l = ms_l * (1.f / 256), mean_h = ms_h * (1.f / 256);
        float rs_l = rsqrtf(mq_l * (1.f / 256) - mean_l * mean_l + 1e-5f);
        float rs_h = rsqrtf(mq_h * (1.f / 256) - mean_h * mean_h + 1e-5f);
        int grl = row0 + rl, grh = row0 + rh;
#pragma unroll
        for (int nj = 0; nj < 8; nj++) {
            int col = wn * 64 + nj * 8 + (lane & 3) * 2;
            float g0 = __ldg(&gamma[col]), g1 = __ldg(&gamma[col + 1]);
            float e0 = __ldg(&beta[col]),  e1 = __ldg(&beta[col + 1]);
            float y0 = (acc[mi][nj][0] - mean_l) * rs_l * g0 + e0;
            float y1 = (acc[mi][nj][1] - mean_l) * rs_l * g1 + e1;
            float y2 = (acc[mi][nj][2] - mean_h) * rs_h * g0 + e0;
            float y3 = (acc[mi][nj][3] - mean_h) * rs_h * g1 + e1;
            if (MODE == 2 || MODE == 3) {
                if (grl < ROWS) *(float2*)(outF + (size_t)grl * 256 + col) = make_float2(y0, y1);
                if (grh < ROWS) *(float2*)(outF + (size_t)grh * 256 + col) = make_float2(y2, y3);
            }
            if (MODE == 1 || MODE == 2) {
                union { __half h[2]; uint32_t u; } pl, ph;
                pl.h[0] = __float2half_rn(y0); pl.h[1] = __float2half_rn(y1);
                ph.h[0] = __float2half_rn(y2); ph.h[1] = __float2half_rn(y3);
                if (grl < ROWS) *(uint32_t*)(outH + (size_t)grl * 256 + col) = pl.u;
                if (grh < ROWS) *(uint32_t*)(outH + (size_t)grh * 256 + col) = ph.u;
            }
        }
    }
}

// ---------------- oa GEMM: BM=128 BN=128, 4 warps, 2 CTAs/SM (as R9) ----------
#define GSTAGE 20480
#define GSMEM  (2 * GSTAGE)

__global__ void __launch_bounds__(128, 2) oagemm_kernel(
    const __half* __restrict__ A, const __half* __restrict__ Bh,
    const float* __restrict__ bias, float* __restrict__ outF)
{
    extern __shared__ __align__(128) char smem[];
    const int tid = threadIdx.x, lane = tid & 31, wid = tid >> 5;
    const int row0 = blockIdx.x * 128;
    const int wm = wid >> 1, wn = wid & 1;
    const uint32_t sbase = smem_u32(smem);

    float acc[4][8][4];
#pragma unroll
    for (int i = 0; i < 4; i++)
#pragma unroll
        for (int j = 0; j < 8; j++)
#pragma unroll
            for (int q = 0; q < 4; q++) acc[i][j][q] = 0.f;

    auto load_stage = [&](int c, int s) {
        const int kk = c * 32;
        const uint32_t st = sbase + s * GSTAGE;
#pragma unroll
        for (int i = 0; i < 4; i++) {
            int g = i * 128 + tid;
            int r = g >> 2, cc = g & 3;
            uint32_t so = (uint32_t)(r * 80 + cc * 16);
            int gr = row0 + r;
            uint32_t sz = (gr < ROWS) ? 16u : 0u;
            cpa16(st + so,         A  + (size_t)gr * 256 + kk + cc * 8, sz);
            cpa16(st + 10240 + so, Bh + (size_t)r * 256 + kk + cc * 8, 16u);
        }
        asm volatile("cp.async.commit_group;" ::: "memory");
    };

    load_stage(0, 0);
    load_stage(1, 1);

#pragma unroll 1
    for (int c = 0; c < 8; c++) {
        if (c < 7) asm volatile("cp.async.wait_group 1;" ::: "memory");
        else       asm volatile("cp.async.wait_group 0;" ::: "memory");
        __syncthreads();

        const uint32_t st = sbase + (c & 1) * GSTAGE;
#pragma unroll
        for (int k16 = 0; k16 < 2; k16++) {
            uint32_t bh[8][2];
            {
                int br = wn * 64 + ((lane >> 4) << 3) + (lane & 7);
                int bc = k16 * 16 + ((lane >> 3) & 1) * 8;
#pragma unroll
                for (int p = 0; p < 4; p++) {
                    uint32_t bd = st + 10240 + (uint32_t)((br + p * 16) * 80 + bc * 2);
                    uint32_t t4[4];
                    ldm_x4(t4, bd);
                    bh[2 * p][0] = t4[0]; bh[2 * p][1] = t4[1];
                    bh[2 * p + 1][0] = t4[2]; bh[2 * p + 1][1] = t4[3];
                }
            }
            int ar = wm * 64 + (lane & 15);
            int ac = k16 * 16 + ((lane >> 4) << 3);
#pragma unroll
            for (int mi = 0; mi < 4; mi++) {
                uint32_t ah[4];
                ldm_x4(ah, st + (uint32_t)((ar + mi * 16) * 80 + ac * 2));
#pragma unroll
                for (int nj = 0; nj < 8; nj++)
                    mma_f16(acc[mi][nj], ah, bh[nj]);
            }
        }
        __syncthreads();
        if (c <= 5) load_stage(c + 2, c & 1);
    }

#pragma unroll
    for (int mi = 0; mi < 4; mi++) {
        int rl = row0 + wm * 64 + mi * 16 + (lane >> 2);
        int rh = rl + 8;
#pragma unroll
        for (int nj = 0; nj < 8; nj++) {
            int col = wn * 64 + nj * 8 + (lane & 3) * 2;
            float b0 = __ldg(&bias[col]), b1 = __ldg(&bias[col + 1]);
            if (rl < ROWS) *(float2*)(outF + (size_t)rl * 128 + col) =
                make_float2(acc[mi][nj][0] + b0, acc[mi][nj][1] + b1);
            if (rh < ROWS) *(float2*)(outF + (size_t)rh * 128 + col) =
                make_float2(acc[mi][nj][2] + b0, acc[mi][nj][3] + b1);
        }
    }
}

// ---------------- launch -------------------------------------------------------
extern "C" void kernel_launch(void* const* d_in, const int* in_sizes, int n_in,
                              void* d_out, int out_size)
{
    const float* tgt       = (const float*)d_in[0];
    const float* query_pos = (const float*)d_in[1];
    const float* refpts    = (const float*)d_in[4];
    const float* src       = (const float*)d_in[6];
    const float* W_dsa = (const float*)d_in[10]; const float* b_dsa = (const float*)d_in[11];
    const float* g_nds = (const float*)d_in[12]; const float* b_nds = (const float*)d_in[13];
    const float* W_off = (const float*)d_in[14]; const float* b_off = (const float*)d_in[15];
    const float* W_att = (const float*)d_in[16]; const float* b_att = (const float*)d_in[17];
    const float* W_val = (const float*)d_in[18]; const float* b_val = (const float*)d_in[19];
    const float* W_out = (const float*)d_in[20]; const float* b_out = (const float*)d_in[21];
    const float* W_csa = (const float*)d_in[22]; const float* b_csa = (const float*)d_in[23];
    const float* g_n1  = (const float*)d_in[24]; const float* b_n1  = (const float*)d_in[25];
    const float* W_ff  = (const float*)d_in[26]; const float* b_ff  = (const float*)d_in[27];
    const float* g_n3  = (const float*)d_in[28]; const float* b_n3  = (const float*)d_in[29];
    float* out = (float*)d_out;

    float *buf0, *buf2, *oa, *boa, *bcomb;
    __half *sf16, *wth, *woah;
    cudaGetSymbolAddress((void**)&buf0,  g_buf0);
    cudaGetSymbolAddress((void**)&buf2,  g_buf2);
    cudaGetSymbolAddress((void**)&oa,    g_oa);
    cudaGetSymbolAddress((void**)&boa,   g_boa);
    cudaGetSymbolAddress((void**)&bcomb, g_bcomb);
    cudaGetSymbolAddress((void**)&sf16,  g_sf16);
    cudaGetSymbolAddress((void**)&wth,   g_wt_h16);
    cudaGetSymbolAddress((void**)&woah,  g_woa_h16);

    cudaFuncSetAttribute((const void*)fgemm_kernel<0>,
                         cudaFuncAttributeMaxDynamicSharedMemorySize, FSMEM);
    cudaFuncSetAttribute((const void*)fgemm_kernel<1>,
                         cudaFuncAttributeMaxDynamicSharedMemorySize, FSMEM);
    cudaFuncSetAttribute((const void*)fgemm_kernel<2>,
                         cudaFuncAttributeMaxDynamicSharedMemorySize, FSMEM);
    cudaFuncSetAttribute((const void*)fgemm_kernel<3>,
                         cudaFuncAttributeMaxDynamicSharedMemorySize, FSMEM);
    cudaFuncSetAttribute((const void*)oagemm_kernel,
                         cudaFuncAttributeMaxDynamicSharedMemorySize, GSMEM);

    const int MT64  = (ROWS + 63) / 64;       // 469 row tiles (fused GEMMs)
    const int MT128 = (ROWS + 127) / 128;     // 235 row tiles (oa GEMM)
    const int EW8   = (ROWS * CDIM / 8 + 255) / 256;

    // 0) combined weight + prep
    comb_kernel<<<256, 256>>>(W_out, W_csa, b_out, b_csa);
    prep_kernel<<<(PREP_TOT + 255) / 256, 256>>>(W_dsa, W_val, W_ff,
                                                 W_off, W_att, b_off, b_att);
    // 1) src -> fp16
    cvt_f16_kernel<<<EW8, 256>>>(src, sf16);
    // 2) dsa GEMM + LN(nds) -> sf16 (in-place safe: CTA owns full rows)
    fgemm_kernel<1><<<MT64, 256, FSMEM>>>(sf16, wth + 0 * 65536, b_dsa,
                                          g_nds, b_nds, nullptr, nullptr, sf16);
    // 3) value GEMM -> buf0 (f32)
    fgemm_kernel<0><<<MT64, 256, FSMEM>>>(sf16, wth + 1 * 65536, b_val,
                                          nullptr, nullptr, nullptr, buf0, nullptr);
    // 4) q = tgt + query_pos -> fp16
    add_f16_kernel<<<EW8, 256>>>(tgt, query_pos, sf16);
    // 5) offsets+attention GEMM (N=128 padded) -> oa
    oagemm_kernel<<<MT128, 128, GSMEM>>>(sf16, woah, boa, oa);
    // 6) deformable sampling -> fp16 (sf16)
    msda_kernel<<<(ROWS * HEADS + 7) / 8, 256>>>(buf0, oa, refpts, sf16);
    // 7) comb GEMM + residual(tgt) + LN(n1) -> buf2 (f32) + sf16
    fgemm_kernel<2><<<MT64, 256, FSMEM>>>(sf16, wth + 2 * 65536, bcomb,
                                          g_n1, b_n1, tgt, buf2, sf16);
    // 8) ff GEMM + gelu + residual(buf2) + LN(n3) -> out
    fgemm_kernel<3><<<MT64, 256, FSMEM>>>(sf16, wth + 3 * 65536, b_ff,
                                          g_n3, b_n3, buf2, out, nullptr);
}

// round 13
// speedup vs baseline: 1.1045x; 1.0150x over previous
#include <cuda_runtime.h>
#include <cuda_fp16.h>
#include <cstdint>
#include <math.h>

// ---------------- problem constants ------------------------------------------
#define BATCH   2
#define LQ      15000
#define ROWS    (BATCH * LQ)      // 30000
#define CDIM    256
#define HEADS   8
#define HDIM    32
#define NPTS    4
#define HL      100
#define WL      150
#define LS      (HL * WL)

// ---------------- scratch ----------------------------------------------------
__device__ __align__(16) float   g_buf0[ROWS * CDIM];
__device__ __align__(16) float   g_buf1[ROWS * CDIM];
__device__ __align__(16) float   g_buf2[ROWS * CDIM];
__device__ __align__(16) float   g_oa  [ROWS * 128];
__device__ __align__(16) __half  g_sf16[ROWS * CDIM];          // fp16 activations
__device__ __align__(16) __half  g_val16[ROWS * CDIM];         // fp16 value tensor
__device__ __align__(16) __half  g_wt_h16[4 * 65536];          // [w][n][k]: dsa,val,comb,ff
__device__ __align__(16) __half  g_woa_h16[128 * 256];
__device__ __align__(16) float   g_boa[128];
__device__ __align__(16) float   g_wcomb[65536];               // W_out @ W_csa (fp32)
__device__ __align__(16) float   g_bcomb[256];

// ---------------- ptx helpers ------------------------------------------------
__device__ __forceinline__ uint32_t smem_u32(const void* p) {
    uint32_t a;
    asm("{ .reg .u64 t; cvta.to.shared.u64 t, %1; cvt.u32.u64 %0, t; }" : "=r"(a) : "l"(p));
    return a;
}
__device__ __forceinline__ void cpa16(uint32_t dst, const void* src, uint32_t sz) {
    asm volatile("cp.async.cg.shared.global [%0], [%1], 16, %2;"
                 :: "r"(dst), "l"(src), "r"(sz));
}
__device__ __forceinline__ void ldm_x4(uint32_t* r, uint32_t addr) {
    asm volatile("ldmatrix.sync.aligned.m8n8.x4.shared.b16 {%0,%1,%2,%3}, [%4];"
                 : "=r"(r[0]), "=r"(r[1]), "=r"(r[2]), "=r"(r[3]) : "r"(addr));
}
__device__ __forceinline__ void mma_f16(float* d, const uint32_t* a, const uint32_t* b) {
    asm volatile("mma.sync.aligned.m16n8k16.row.col.f32.f16.f16.f32 "
        "{%0,%1,%2,%3}, {%4,%5,%6,%7}, {%8,%9}, {%0,%1,%2,%3};"
        : "+f"(d[0]), "+f"(d[1]), "+f"(d[2]), "+f"(d[3])
        : "r"(a[0]), "r"(a[1]), "r"(a[2]), "r"(a[3]), "r"(b[0]), "r"(b[1]));
}

// ---------------- W_comb = W_out @ W_csa, b_comb = b_out @ W_csa + b_csa ------
__global__ void comb_kernel(const float* __restrict__ Wo, const float* __restrict__ Wc,
                            const float* __restrict__ bo, const float* __restrict__ bc)
{
    const int n = threadIdx.x;
    const int k = blockIdx.x;
    float s = 0.f;
#pragma unroll 8
    for (int j = 0; j < 256; j++) s = fmaf(Wo[k * 256 + j], Wc[j * 256 + n], s);
    g_wcomb[k * 256 + n] = s;
    if (k == 0) {
        float sb = 0.f;
#pragma unroll 8
        for (int j = 0; j < 256; j++) sb = fmaf(bo[j], Wc[j * 256 + n], sb);
        g_bcomb[n] = sb + bc[n];
    }
}

// ---------------- weight prep: transpose + fp16 -------------------------------
#define PREP_TOT (4 * 65536 + 128 * 256 + 128)
__global__ void prep_kernel(const float* __restrict__ Wd, const float* __restrict__ Wv,
                            const float* __restrict__ Wf, const float* __restrict__ Woff,
                            const float* __restrict__ Watt, const float* __restrict__ boff,
                            const float* __restrict__ batt)
{
    int idx = blockIdx.x * 256 + threadIdx.x;
    if (idx < 4 * 65536) {
        int w = idx >> 16, e = idx & 65535, n = e >> 8, k = e & 255;
        float v;
        if (w == 0)      v = Wd[k * 256 + n];
        else if (w == 1) v = Wv[k * 256 + n];
        else if (w == 2) v = g_wcomb[k * 256 + n];
        else             v = Wf[k * 256 + n];
        g_wt_h16[w * 65536 + n * 256 + k] = __float2half_rn(v);
    } else if (idx < 4 * 65536 + 128 * 256) {
        int e = idx - 4 * 65536, n = e >> 8, k = e & 255;
        float v = 0.f;
        if (n < 64)       v = Woff[k * 64 + n];
        else if (n < 96)  v = Watt[k * 32 + (n - 64)];
        g_woa_h16[n * 256 + k] = __float2half_rn(v);
    } else if (idx < PREP_TOT) {
        int j = idx - (4 * 65536 + 128 * 256);
        g_boa[j] = (j < 64) ? boff[j] : (j < 96 ? batt[j - 64] : 0.f);
    }
}

// ---------------- elementwise conversion kernels ------------------------------
__global__ void cvt_f16_kernel(const float* __restrict__ x, __half* __restrict__ o)
{
    int base = (blockIdx.x * 256 + threadIdx.x) * 8;
    if (base >= ROWS * CDIM) return;
    float4 v0 = *(const float4*)(x + base);
    float4 v1 = *(const float4*)(x + base + 4);
    union { __half h[8]; uint4 u; } p;
    p.h[0] = __float2half_rn(v0.x); p.h[1] = __float2half_rn(v0.y);
    p.h[2] = __float2half_rn(v0.z); p.h[3] = __float2half_rn(v0.w);
    p.h[4] = __float2half_rn(v1.x); p.h[5] = __float2half_rn(v1.y);
    p.h[6] = __float2half_rn(v1.z); p.h[7] = __float2half_rn(v1.w);
    *(uint4*)(o + base) = p.u;
}

__global__ void add_f16_kernel(const float* __restrict__ a, const float* __restrict__ b,
                               __half* __restrict__ o)
{
    int base = (blockIdx.x * 256 + threadIdx.x) * 8;
    if (base >= ROWS * CDIM) return;
    float4 a0 = *(const float4*)(a + base), a1 = *(const float4*)(a + base + 4);
    float4 b0 = *(const float4*)(b + base), b1 = *(const float4*)(b + base + 4);
    union { __half h[8]; uint4 u; } p;
    p.h[0] = __float2half_rn(a0.x + b0.x); p.h[1] = __float2half_rn(a0.y + b0.y);
    p.h[2] = __float2half_rn(a0.z + b0.z); p.h[3] = __float2half_rn(a0.w + b0.w);
    p.h[4] = __float2half_rn(a1.x + b1.x); p.h[5] = __float2half_rn(a1.y + b1.y);
    p.h[6] = __float2half_rn(a1.z + b1.z); p.h[7] = __float2half_rn(a1.w + b1.w);
    *(uint4*)(o + base) = p.u;
}

// ---------------- warp-per-row layernorm kernels ------------------------------
__device__ __forceinline__ float warp_sum(float v)
{
#pragma unroll
    for (int o = 16; o > 0; o >>= 1) v += __shfl_xor_sync(0xffffffffu, v, o);
    return v;
}

__global__ void ln_f16_warp(const float* __restrict__ x, const float* __restrict__ g,
                            const float* __restrict__ b, __half* __restrict__ o)
{
    const int w = threadIdx.x >> 5, lane = threadIdx.x & 31;
    const int row = blockIdx.x * 8 + w;
    const float4* xr = (const float4*)(x + (size_t)row * 256) + lane * 2;
    float4 v0 = xr[0], v1 = xr[1];
    float vv[8] = {v0.x, v0.y, v0.z, v0.w, v1.x, v1.y, v1.z, v1.w};
    float s = 0.f;
#pragma unroll
    for (int i = 0; i < 8; i++) s += vv[i];
    float mean = warp_sum(s) * (1.f / 256);
    float va = 0.f;
#pragma unroll
    for (int i = 0; i < 8; i++) { vv[i] -= mean; va += vv[i] * vv[i]; }
    float rs = rsqrtf(warp_sum(va) * (1.f / 256) + 1e-5f);
    float4 g0 = ((const float4*)g)[lane * 2], g1 = ((const float4*)g)[lane * 2 + 1];
    float4 b0 = ((const float4*)b)[lane * 2], b1 = ((const float4*)b)[lane * 2 + 1];
    float gg[8] = {g0.x, g0.y, g0.z, g0.w, g1.x, g1.y, g1.z, g1.w};
    float bb[8] = {b0.x, b0.y, b0.z, b0.w, b1.x, b1.y, b1.z, b1.w};
    union { __half h[8]; uint4 u; } p;
#pragma unroll
    for (int i = 0; i < 8; i++) p.h[i] = __float2half_rn(vv[i] * rs * gg[i] + bb[i]);
    *(uint4*)(o + (size_t)row * 256 + lane * 8) = p.u;
}

__global__ void addln_f16_warp(const float* __restrict__ a, const float* __restrict__ c,
                               const float* __restrict__ g, const float* __restrict__ b,
                               float* __restrict__ y, __half* __restrict__ o)
{
    const int w = threadIdx.x >> 5, lane = threadIdx.x & 31;
    const int row = blockIdx.x * 8 + w;
    const float4* ar = (const float4*)(a + (size_t)row * 256) + lane * 2;
    const float4* cr = (const float4*)(c + (size_t)row * 256) + lane * 2;
    float4 a0 = ar[0], a1 = ar[1], c0 = cr[0], c1 = cr[1];
    float vv[8] = {a0.x + c0.x, a0.y + c0.y, a0.z + c0.z, a0.w + c0.w,
                   a1.x + c1.x, a1.y + c1.y, a1.z + c1.z, a1.w + c1.w};
    float s = 0.f;
#pragma unroll
    for (int i = 0; i < 8; i++) s += vv[i];
    float mean = warp_sum(s) * (1.f / 256);
    float va = 0.f;
#pragma unroll
    for (int i = 0; i < 8; i++) { vv[i] -= mean; va += vv[i] * vv[i]; }
    float rs = rsqrtf(warp_sum(va) * (1.f / 256) + 1e-5f);
    float4 g0 = ((const float4*)g)[lane * 2], g1 = ((const float4*)g)[lane * 2 + 1];
    float4 b0 = ((const float4*)b)[lane * 2], b1 = ((const float4*)b)[lane * 2 + 1];
    float gg[8] = {g0.x, g0.y, g0.z, g0.w, g1.x, g1.y, g1.z, g1.w};
    float bb[8] = {b0.x, b0.y, b0.z, b0.w, b1.x, b1.y, b1.z, b1.w};
    union { __half h[8]; uint4 u; } p;
    float out8[8];
#pragma unroll
    for (int i = 0; i < 8; i++) {
        float t = vv[i] * rs * gg[i] + bb[i];
        out8[i] = t;
        p.h[i] = __float2half_rn(t);
    }
    float4* yr = (float4*)(y + (size_t)row * 256) + lane * 2;
    yr[0] = make_float4(out8[0], out8[1], out8[2], out8[3]);
    yr[1] = make_float4(out8[4], out8[5], out8[6], out8[7]);
    *(uint4*)(o + (size_t)row * 256 + lane * 8) = p.u;
}

__global__ void addln_warp(const float* __restrict__ a, const float* __restrict__ c,
                           const float* __restrict__ g, const float* __restrict__ b,
                           float* __restrict__ y)
{
    const int w = threadIdx.x >> 5, lane = threadIdx.x & 31;
    const int row = blockIdx.x * 8 + w;
    const float4* ar = (const float4*)(a + (size_t)row * 256) + lane * 2;
    const float4* cr = (const float4*)(c + (size_t)row * 256) + lane * 2;
    float4 a0 = ar[0], a1 = ar[1], c0 = cr[0], c1 = cr[1];
    float vv[8] = {a0.x + c0.x, a0.y + c0.y, a0.z + c0.z, a0.w + c0.w,
                   a1.x + c1.x, a1.y + c1.y, a1.z + c1.z, a1.w + c1.w};
    float s = 0.f;
#pragma unroll
    for (int i = 0; i < 8; i++) s += vv[i];
    float mean = warp_sum(s) * (1.f / 256);
    float va = 0.f;
#pragma unroll
    for (int i = 0; i < 8; i++) { vv[i] -= mean; va += vv[i] * vv[i]; }
    float rs = rsqrtf(warp_sum(va) * (1.f / 256) + 1e-5f);
    float4 g0 = ((const float4*)g)[lane * 2], g1 = ((const float4*)g)[lane * 2 + 1];
    float4 b0 = ((const float4*)b)[lane * 2], b1 = ((const float4*)b)[lane * 2 + 1];
    float gg[8] = {g0.x, g0.y, g0.z, g0.w, g1.x, g1.y, g1.z, g1.w};
    float bb[8] = {b0.x, b0.y, b0.z, b0.w, b1.x, b1.y, b1.z, b1.w};
    float out8[8];
#pragma unroll
    for (int i = 0; i < 8; i++) out8[i] = vv[i] * rs * gg[i] + bb[i];
    float4* yr = (float4*)(y + (size_t)row * 256) + lane * 2;
    yr[0] = make_float4(out8[0], out8[1], out8[2], out8[3]);
    yr[1] = make_float4(out8[4], out8[5], out8[6], out8[7]);
}

// ---------------- deformable sampling (fp16 value) ----------------------------
__device__ __forceinline__ float fetch_vh(const __half* __restrict__ vbase, int x, int y)
{
    if (x < 0 || x >= WL || y < 0 || y >= HL) return 0.f;
    return __half2float(vbase[(size_t)(y * WL + x) * CDIM]);
}

__global__ void msda_kernel(const __half* __restrict__ value, const float* __restrict__ oa,
                            const float* __restrict__ ref, __half* __restrict__ o)
{
    const int warp = blockIdx.x * (blockDim.x >> 5) + (threadIdx.x >> 5);
    const int lane = threadIdx.x & 31;
    if (warp >= ROWS * HEADS) return;
    const int hd = warp & 7;
    const int bq = warp >> 3;
    const int b  = bq / LQ;

    const float* oarow = oa + (size_t)bq * 128;
    float a0 = oarow[64 + hd * 4 + 0];
    float a1 = oarow[64 + hd * 4 + 1];
    float a2 = oarow[64 + hd * 4 + 2];
    float a3 = oarow[64 + hd * 4 + 3];
    float m  = fmaxf(fmaxf(a0, a1), fmaxf(a2, a3));
    float e0 = expf(a0 - m), e1 = expf(a1 - m), e2 = expf(a2 - m), e3 = expf(a3 - m);
    float inv = 1.f / (e0 + e1 + e2 + e3);
    float w[4] = {e0 * inv, e1 * inv, e2 * inv, e3 * inv};

    const float rx = ref[(size_t)bq * 2 + 0];
    const float ry = ref[(size_t)bq * 2 + 1];
    const __half* vbase = value + (size_t)b * LS * CDIM + hd * HDIM + lane;

    float acc = 0.f;
#pragma unroll
    for (int p = 0; p < NPTS; p++) {
        float ox = oarow[hd * 8 + p * 2 + 0];
        float oy = oarow[hd * 8 + p * 2 + 1];
        float X = (rx + ox / (float)WL) * (float)WL - 0.5f;
        float Y = (ry + oy / (float)HL) * (float)HL - 0.5f;
        float x0f = floorf(X), y0f = floorf(Y);
        float lx = X - x0f, ly = Y - y0f;
        int x0 = (int)x0f, y0 = (int)y0f;
        float s00 = fetch_vh(vbase, x0,     y0);
        float s10 = fetch_vh(vbase, x0 + 1, y0);
        float s01 = fetch_vh(vbase, x0,     y0 + 1);
        float s11 = fetch_vh(vbase, x0 + 1, y0 + 1);
        float sv  = s00 * (1.f - lx) * (1.f - ly) + s10 * lx * (1.f - ly)
                  + s01 * (1.f - lx) * ly         + s11 * lx * ly;
        acc = fmaf(w[p], sv, acc);
    }
    o[(size_t)bq * CDIM + hd * HDIM + lane] = __float2half_rn(acc);
}

// ---------------- mma.sync fp16 GEMM (128 threads, 4 warps, 64x64 tiles) ------
// C[ROWS, N] = A16 @ Wh^T + bias   (W stored [n][k], K contiguous)
// OUT = 0: f32, 1: fp16.  GELU optional.
// BM=128 BN=128 BK=32, 2-stage cp.async, 2 CTAs/SM.
#define GSTAGE 20480
#define GSMEM  (2 * GSTAGE)

template<bool GELU, int OUT>
__global__ void __launch_bounds__(128, 2) mgemm_kernel(
    const __half* __restrict__ A, const __half* __restrict__ Bh,
    const float* __restrict__ bias,
    float* __restrict__ outF, __half* __restrict__ outH, int ldo)
{
    extern __shared__ __align__(128) char smem[];
    const int tid = threadIdx.x, lane = tid & 31, wid = tid >> 5;
    const int row0 = blockIdx.x * 128, n0 = blockIdx.y * 128;
    const int wm = wid >> 1, wn = wid & 1;
    const uint32_t sbase = smem_u32(smem);

    float acc[4][8][4];
#pragma unroll
    for (int i = 0; i < 4; i++)
#pragma unroll
        for (int j = 0; j < 8; j++)
#pragma unroll
            for (int q = 0; q < 4; q++) acc[i][j][q] = 0.f;

    auto load_stage = [&](int c, int s) {
        const int kk = c * 32;
        const uint32_t st = sbase + s * GSTAGE;
#pragma unroll
        for (int i = 0; i < 4; i++) {
            int g = i * 128 + tid;
            int r = g >> 2, cc = g & 3;
            uint32_t so = (uint32_t)(r * 80 + cc * 16);
            int gr = row0 + r;
            uint32_t sz = (gr < ROWS) ? 16u : 0u;
            cpa16(st + so,         A  + (size_t)gr * 256 + kk + cc * 8, sz);
            cpa16(st + 10240 + so, Bh + (size_t)(n0 + r) * 256 + kk + cc * 8, 16u);
        }
        asm volatile("cp.async.commit_group;" ::: "memory");
    };

    load_stage(0, 0);
    load_stage(1, 1);

#pragma unroll 1
    for (int c = 0; c < 8; c++) {
        if (c < 7) asm volatile("cp.async.wait_group 1;" ::: "memory");
        else       asm volatile("cp.async.wait_group 0;" ::: "memory");
        __syncthreads();

        const uint32_t st = sbase + (c & 1) * GSTAGE;
#pragma unroll
        for (int k16 = 0; k16 < 2; k16++) {
            uint32_t bh[8][2];
            {
                int br = wn * 64 + ((lane >> 4) << 3) + (lane & 7);
                int bc = k16 * 16 + ((lane >> 3) & 1) * 8;
#pragma unroll
                for (int p = 0; p < 4; p++) {
                    uint32_t bd = st + 10240 + (uint32_t)((br + p * 16) * 80 + bc * 2);
                    uint32_t t4[4];
                    ldm_x4(t4, bd);
                    bh[2 * p][0] = t4[0]; bh[2 * p][1] = t4[1];
                    bh[2 * p + 1][0] = t4[2]; bh[2 * p + 1][1] = t4[3];
                }
            }
            int ar = wm * 64 + (lane & 15);
            int ac = k16 * 16 + ((lane >> 4) << 3);
#pragma unroll
            for (int mi = 0; mi < 4; mi++) {
                uint32_t ah[4];
                ldm_x4(ah, st + (uint32_t)((ar + mi * 16) * 80 + ac * 2));
#pragma unroll
                for (int nj = 0; nj < 8; nj++)
                    mma_f16(acc[mi][nj], ah, bh[nj]);
            }
        }
        __syncthreads();
        if (c <= 5) load_stage(c + 2, c & 1);
    }

#pragma unroll
    for (int mi = 0; mi < 4; mi++) {
        int rl = row0 + wm * 64 + mi * 16 + (lane >> 2);
        int rh = rl + 8;
#pragma unroll
        for (int nj = 0; nj < 8; nj++) {
            int col = n0 + wn * 64 + nj * 8 + (lane & 3) * 2;
            float b0 = __ldg(&bias[col]), b1 = __ldg(&bias[col + 1]);
            float v0 = acc[mi][nj][0] + b0, v1 = acc[mi][nj][1] + b1;
            float v2 = acc[mi][nj][2] + b0, v3 = acc[mi][nj][3] + b1;
            if (GELU) {
                v0 = 0.5f * v0 * (1.f + erff(v0 * 0.70710678118654752f));
                v1 = 0.5f * v1 * (1.f + erff(v1 * 0.70710678118654752f));
                v2 = 0.5f * v2 * (1.f + erff(v2 * 0.70710678118654752f));
                v3 = 0.5f * v3 * (1.f + erff(v3 * 0.70710678118654752f));
            }
            if (OUT == 0) {
                if (rl < ROWS) *(float2*)(outF + (size_t)rl * ldo + col) = make_float2(v0, v1);
                if (rh < ROWS) *(float2*)(outF + (size_t)rh * ldo + col) = make_float2(v2, v3);
            } else {
                union { __half h[2]; uint32_t u; } pl, ph;
                pl.h[0] = __float2half_rn(v0); pl.h[1] = __float2half_rn(v1);
                ph.h[0] = __float2half_rn(v2); ph.h[1] = __float2half_rn(v3);
                if (rl < ROWS) *(uint32_t*)(outH + (size_t)rl * ldo + col) = pl.u;
                if (rh < ROWS) *(uint32_t*)(outH + (size_t)rh * ldo + col) = ph.u;
            }
        }
    }
}

// ---------------- launch -------------------------------------------------------
extern "C" void kernel_launch(void* const* d_in, const int* in_sizes, int n_in,
                              void* d_out, int out_size)
{
    const float* tgt       = (const float*)d_in[0];
    const float* query_pos = (const float*)d_in[1];
    const float* refpts    = (const float*)d_in[4];
    const float* src       = (const float*)d_in[6];
    const float* W_dsa = (const float*)d_in[10]; const float* b_dsa = (const float*)d_in[11];
    const float* g_nds = (const float*)d_in[12]; const float* b_nds = (const float*)d_in[13];
    const float* W_off = (const float*)d_in[14]; const float* b_off = (const float*)d_in[15];
    const float* W_att = (const float*)d_in[16]; const float* b_att = (const float*)d_in[17];
    const float* W_val = (const float*)d_in[18]; const float* b_val = (const float*)d_in[19];
    const float* W_out = (const float*)d_in[20]; const float* b_out = (const float*)d_in[21];
    const float* W_csa = (const float*)d_in[22]; const float* b_csa = (const float*)d_in[23];
    const float* g_n1  = (const float*)d_in[24]; const float* b_n1  = (const float*)d_in[25];
    const float* W_ff  = (const float*)d_in[26]; const float* b_ff  = (const float*)d_in[27];
    const float* g_n3  = (const float*)d_in[28]; const float* b_n3  = (const float*)d_in[29];
    float* out = (float*)d_out;

    float *buf0, *buf1, *buf2, *oa, *boa, *bcomb;
    __half *sf16, *val16, *wth, *woah;
    cudaGetSymbolAddress((void**)&buf0,  g_buf0);
    cudaGetSymbolAddress((void**)&buf1,  g_buf1);
    cudaGetSymbolAddress((void**)&buf2,  g_buf2);
    cudaGetSymbolAddress((void**)&oa,    g_oa);
    cudaGetSymbolAddress((void**)&boa,   g_boa);
    cudaGetSymbolAddress((void**)&bcomb, g_bcomb);
    cudaGetSymbolAddress((void**)&sf16,  g_sf16);
    cudaGetSymbolAddress((void**)&val16, g_val16);
    cudaGetSymbolAddress((void**)&wth,   g_wt_h16);
    cudaGetSymbolAddress((void**)&woah,  g_woa_h16);

    cudaFuncSetAttribute((const void*)mgemm_kernel<false, 0>,
                         cudaFuncAttributeMaxDynamicSharedMemorySize, GSMEM);
    cudaFuncSetAttribute((const void*)mgemm_kernel<false, 1>,
                         cudaFuncAttributeMaxDynamicSharedMemorySize, GSMEM);
    cudaFuncSetAttribute((const void*)mgemm_kernel<true, 0>,
                         cudaFuncAttributeMaxDynamicSharedMemorySize, GSMEM);

    const int MT  = (ROWS + 127) / 128;       // 235 row tiles
    const dim3 gFull(MT, 2);                  // N = 256
    const dim3 gOA  (MT, 1);                  // N = 128 (96 padded)
    const int EW8 = (ROWS * CDIM / 8 + 255) / 256;
    const int LNB = ROWS / 8;

    // 0) combined weight + prep
    comb_kernel<<<256, 256>>>(W_out, W_csa, b_out, b_csa);
    prep_kernel<<<(PREP_TOT + 255) / 256, 256>>>(W_dsa, W_val, W_ff,
                                                 W_off, W_att, b_off, b_att);
    // 1) src -> fp16
    cvt_f16_kernel<<<EW8, 256>>>(src, sf16);
    // 2) dsa GEMM -> buf0 (f32)
    mgemm_kernel<false, 0><<<gFull, 128, GSMEM>>>(
        sf16, wth + 0 * 65536, b_dsa, buf0, nullptr, 256);
    // 3) LN(nds) -> fp16
    ln_f16_warp<<<LNB, 256>>>(buf0, g_nds, b_nds, sf16);
    // 4) value GEMM -> val16 (fp16!)
    mgemm_kernel<false, 1><<<gFull, 128, GSMEM>>>(
        sf16, wth + 1 * 65536, b_val, nullptr, val16, 256);
    // 5) q = tgt + query_pos -> fp16
    add_f16_kernel<<<EW8, 256>>>(tgt, query_pos, sf16);
    // 6) offsets+attention GEMM (N=128 padded) -> oa
    mgemm_kernel<false, 0><<<gOA, 128, GSMEM>>>(
        sf16, woah, boa, oa, nullptr, 128);
    // 7) deformable sampling (fp16 value) -> fp16 (sf16)
    msda_kernel<<<(ROWS * HEADS + 7) / 8, 256>>>(val16, oa, refpts, sf16);
    // 8) combined out+csa GEMM -> buf1 (f32)
    mgemm_kernel<false, 0><<<gFull, 128, GSMEM>>>(
        sf16, wth + 2 * 65536, bcomb, buf1, nullptr, 256);
    // 9) t = LN(tgt + tgt2) -> buf2 (f32) + fp16
    addln_f16_warp<<<LNB, 256>>>(tgt, buf1, g_n1, b_n1, buf2, sf16);
    // 10) ff = gelu(t @ W_ff + b_ff) -> buf0 (f32)
    mgemm_kernel<true, 0><<<gFull, 128, GSMEM>>>(
        sf16, wth + 3 * 65536, b_ff, buf0, nullptr, 256);
    // 11) out = LN(t + ff)
    addln_warp<<<LNB, 256>>>(buf2, buf0, g_n3, b_n3, out);
}

// round 14
// speedup vs baseline: 1.1231x; 1.0168x over previous
#include <cuda_runtime.h>
#include <cuda_fp16.h>
#include <cstdint>
#include <math.h>

// ---------------- problem constants ------------------------------------------
#define BATCH   2
#define LQ      15000
#define ROWS    (BATCH * LQ)      // 30000
#define CDIM    256
#define HEADS   8
#define HDIM    32
#define NPTS    4
#define HL      100
#define WL      150
#define LS      (HL * WL)

// ---------------- scratch ----------------------------------------------------
__device__ __align__(16) float   g_buf0[ROWS * CDIM];          // f32 value tensor
__device__ __align__(16) float   g_buf2[ROWS * CDIM];          // f32 t
__device__ __align__(16) float   g_oa  [ROWS * 128];
__device__ __align__(16) __half  g_sf16[ROWS * CDIM];          // fp16 activations
__device__ __align__(16) __half  g_q16 [ROWS * CDIM];          // fp16 q = tgt+query_pos
__device__ __align__(16) __half  g_h16b[ROWS * CDIM];          // fp16 gemm outputs
__device__ __align__(16) __half  g_wt_h16[4 * 65536];          // [w][n][k]: dsa,val,comb,ff
__device__ __align__(16) __half  g_woa_h16[128 * 256];
__device__ __align__(16) float   g_boa[128];
__device__ __align__(16) float   g_wcomb[65536];               // W_out @ W_csa (fp32)
__device__ __align__(16) float   g_bcomb[256];

// ---------------- ptx helpers ------------------------------------------------
__device__ __forceinline__ uint32_t smem_u32(const void* p) {
    uint32_t a;
    asm("{ .reg .u64 t; cvta.to.shared.u64 t, %1; cvt.u32.u64 %0, t; }" : "=r"(a) : "l"(p));
    return a;
}
__device__ __forceinline__ void cpa16(uint32_t dst, const void* src, uint32_t sz) {
    asm volatile("cp.async.cg.shared.global [%0], [%1], 16, %2;"
                 :: "r"(dst), "l"(src), "r"(sz));
}
__device__ __forceinline__ void ldm_x4(uint32_t* r, uint32_t addr) {
    asm volatile("ldmatrix.sync.aligned.m8n8.x4.shared.b16 {%0,%1,%2,%3}, [%4];"
                 : "=r"(r[0]), "=r"(r[1]), "=r"(r[2]), "=r"(r[3]) : "r"(addr));
}
__device__ __forceinline__ void mma_f16(float* d, const uint32_t* a, const uint32_t* b) {
    asm volatile("mma.sync.aligned.m16n8k16.row.col.f32.f16.f16.f32 "
        "{%0,%1,%2,%3}, {%4,%5,%6,%7}, {%8,%9}, {%0,%1,%2,%3};"
        : "+f"(d[0]), "+f"(d[1]), "+f"(d[2]), "+f"(d[3])
        : "r"(a[0]), "r"(a[1]), "r"(a[2]), "r"(a[3]), "r"(b[0]), "r"(b[1]));
}

// ---------------- W_comb = W_out @ W_csa, b_comb = b_out @ W_csa + b_csa ------
__global__ void comb_kernel(const float* __restrict__ Wo, const float* __restrict__ Wc,
                            const float* __restrict__ bo, const float* __restrict__ bc)
{
    const int n = threadIdx.x;
    const int k = blockIdx.x;
    float s = 0.f;
#pragma unroll 8
    for (int j = 0; j < 256; j++) s = fmaf(Wo[k * 256 + j], Wc[j * 256 + n], s);
    g_wcomb[k * 256 + n] = s;
    if (k == 0) {
        float sb = 0.f;
#pragma unroll 8
        for (int j = 0; j < 256; j++) sb = fmaf(bo[j], Wc[j * 256 + n], sb);
        g_bcomb[n] = sb + bc[n];
    }
}

// ---------------- weight prep: transpose + fp16 -------------------------------
#define PREP_TOT (4 * 65536 + 128 * 256 + 128)
__global__ void prep_kernel(const float* __restrict__ Wd, const float* __restrict__ Wv,
                            const float* __restrict__ Wf, const float* __restrict__ Woff,
                            const float* __restrict__ Watt, const float* __restrict__ boff,
                            const float* __restrict__ batt)
{
    int idx = blockIdx.x * 256 + threadIdx.x;
    if (idx < 4 * 65536) {
        int w = idx >> 16, e = idx & 65535, n = e >> 8, k = e & 255;
        float v;
        if (w == 0)      v = Wd[k * 256 + n];
        else if (w == 1) v = Wv[k * 256 + n];
        else if (w == 2) v = g_wcomb[k * 256 + n];
        else             v = Wf[k * 256 + n];
        g_wt_h16[w * 65536 + n * 256 + k] = __float2half_rn(v);
    } else if (idx < 4 * 65536 + 128 * 256) {
        int e = idx - 4 * 65536, n = e >> 8, k = e & 255;
        float v = 0.f;
        if (n < 64)       v = Woff[k * 64 + n];
        else if (n < 96)  v = Watt[k * 32 + (n - 64)];
        g_woa_h16[n * 256 + k] = __float2half_rn(v);
    } else if (idx < PREP_TOT) {
        int j = idx - (4 * 65536 + 128 * 256);
        g_boa[j] = (j < 64) ? boff[j] : (j < 96 ? batt[j - 64] : 0.f);
    }
}

// ---------------- activation prep: src->fp16, tgt+qp->fp16 --------------------
__global__ void prep_act_kernel(const float* __restrict__ src, const float* __restrict__ tgt,
                                const float* __restrict__ qp,
                                __half* __restrict__ s16, __half* __restrict__ q16)
{
    int base = (blockIdx.x * 256 + threadIdx.x) * 8;
    if (base >= ROWS * CDIM) return;
    float4 s0 = *(const float4*)(src + base), s1 = *(const float4*)(src + base + 4);
    union { __half h[8]; uint4 u; } p;
    p.h[0] = __float2half_rn(s0.x); p.h[1] = __float2half_rn(s0.y);
    p.h[2] = __float2half_rn(s0.z); p.h[3] = __float2half_rn(s0.w);
    p.h[4] = __float2half_rn(s1.x); p.h[5] = __float2half_rn(s1.y);
    p.h[6] = __float2half_rn(s1.z); p.h[7] = __float2half_rn(s1.w);
    *(uint4*)(s16 + base) = p.u;
    float4 a0 = *(const float4*)(tgt + base), a1 = *(const float4*)(tgt + base + 4);
    float4 b0 = *(const float4*)(qp + base),  b1 = *(const float4*)(qp + base + 4);
    p.h[0] = __float2half_rn(a0.x + b0.x); p.h[1] = __float2half_rn(a0.y + b0.y);
    p.h[2] = __float2half_rn(a0.z + b0.z); p.h[3] = __float2half_rn(a0.w + b0.w);
    p.h[4] = __float2half_rn(a1.x + b1.x); p.h[5] = __float2half_rn(a1.y + b1.y);
    p.h[6] = __float2half_rn(a1.z + b1.z); p.h[7] = __float2half_rn(a1.w + b1.w);
    *(uint4*)(q16 + base) = p.u;
}

// ---------------- warp-per-row layernorm kernels ------------------------------
__device__ __forceinline__ float warp_sum(float v)
{
#pragma unroll
    for (int o = 16; o > 0; o >>= 1) v += __shfl_xor_sync(0xffffffffu, v, o);
    return v;
}

// fp16 in -> LN -> fp16 out
__global__ void ln_h_warp(const __half* __restrict__ x, const float* __restrict__ g,
                          const float* __restrict__ b, __half* __restrict__ o)
{
    const int w = threadIdx.x >> 5, lane = threadIdx.x & 31;
    const int row = blockIdx.x * 8 + w;
    union { __half h[8]; uint4 u; } in;
    in.u = *(const uint4*)(x + (size_t)row * 256 + lane * 8);
    float vv[8];
#pragma unroll
    for (int i = 0; i < 8; i++) vv[i] = __half2float(in.h[i]);
    float s = 0.f;
#pragma unroll
    for (int i = 0; i < 8; i++) s += vv[i];
    float mean = warp_sum(s) * (1.f / 256);
    float va = 0.f;
#pragma unroll
    for (int i = 0; i < 8; i++) { vv[i] -= mean; va += vv[i] * vv[i]; }
    float rs = rsqrtf(warp_sum(va) * (1.f / 256) + 1e-5f);
    float4 g0 = ((const float4*)g)[lane * 2], g1 = ((const float4*)g)[lane * 2 + 1];
    float4 b0 = ((const float4*)b)[lane * 2], b1 = ((const float4*)b)[lane * 2 + 1];
    float gg[8] = {g0.x, g0.y, g0.z, g0.w, g1.x, g1.y, g1.z, g1.w};
    float bb[8] = {b0.x, b0.y, b0.z, b0.w, b1.x, b1.y, b1.z, b1.w};
    union { __half h[8]; uint4 u; } p;
#pragma unroll
    for (int i = 0; i < 8; i++) p.h[i] = __float2half_rn(vv[i] * rs * gg[i] + bb[i]);
    *(uint4*)(o + (size_t)row * 256 + lane * 8) = p.u;
}

// t = LN(a_f32 + c_fp16) -> y(f32) + o(fp16)
__global__ void addln_h2_warp(const float* __restrict__ a, const __half* __restrict__ c,
                              const float* __restrict__ g, const float* __restrict__ b,
                              float* __restrict__ y, __half* __restrict__ o)
{
    const int w = threadIdx.x >> 5, lane = threadIdx.x & 31;
    const int row = blockIdx.x * 8 + w;
    const float4* ar = (const float4*)(a + (size_t)row * 256) + lane * 2;
    float4 a0 = ar[0], a1 = ar[1];
    union { __half h[8]; uint4 u; } ch;
    ch.u = *(const uint4*)(c + (size_t)row * 256 + lane * 8);
    float vv[8] = {a0.x + __half2float(ch.h[0]), a0.y + __half2float(ch.h[1]),
                   a0.z + __half2float(ch.h[2]), a0.w + __half2float(ch.h[3]),
                   a1.x + __half2float(ch.h[4]), a1.y + __half2float(ch.h[5]),
                   a1.z + __half2float(ch.h[6]), a1.w + __half2float(ch.h[7])};
    float s = 0.f;
#pragma unroll
    for (int i = 0; i < 8; i++) s += vv[i];
    float mean = warp_sum(s) * (1.f / 256);
    float va = 0.f;
#pragma unroll
    for (int i = 0; i < 8; i++) { vv[i] -= mean; va += vv[i] * vv[i]; }
    float rs = rsqrtf(warp_sum(va) * (1.f / 256) + 1e-5f);
    float4 g0 = ((const float4*)g)[lane * 2], g1 = ((const float4*)g)[lane * 2 + 1];
    float4 b0 = ((const float4*)b)[lane * 2], b1 = ((const float4*)b)[lane * 2 + 1];
    float gg[8] = {g0.x, g0.y, g0.z, g0.w, g1.x, g1.y, g1.z, g1.w};
    float bb[8] = {b0.x, b0.y, b0.z, b0.w, b1.x, b1.y, b1.z, b1.w};
    union { __half h[8]; uint4 u; } p;
    float out8[8];
#pragma unroll
    for (int i = 0; i < 8; i++) {
        float t = vv[i] * rs * gg[i] + bb[i];
        out8[i] = t;
        p.h[i] = __float2half_rn(t);
    }
    float4* yr = (float4*)(y + (size_t)row * 256) + lane * 2;
    yr[0] = make_float4(out8[0], out8[1], out8[2], out8[3]);
    yr[1] = make_float4(out8[4], out8[5], out8[6], out8[7]);
    *(uint4*)(o + (size_t)row * 256 + lane * 8) = p.u;
}

// y = LN(a_f32 + c_fp16) (f32 only)
__global__ void addln_h_warp(const float* __restrict__ a, const __half* __restrict__ c,
                             const float* __restrict__ g, const float* __restrict__ b,
                             float* __restrict__ y)
{
    const int w = threadIdx.x >> 5, lane = threadIdx.x & 31;
    const int row = blockIdx.x * 8 + w;
    const float4* ar = (const float4*)(a + (size_t)row * 256) + lane * 2;
    float4 a0 = ar[0], a1 = ar[1];
    union { __half h[8]; uint4 u; } ch;
    ch.u = *(const uint4*)(c + (size_t)row * 256 + lane * 8);
    float vv[8] = {a0.x + __half2float(ch.h[0]), a0.y + __half2float(ch.h[1]),
                   a0.z + __half2float(ch.h[2]), a0.w + __half2float(ch.h[3]),
                   a1.x + __half2float(ch.h[4]), a1.y + __half2float(ch.h[5]),
                   a1.z + __half2float(ch.h[6]), a1.w + __half2float(ch.h[7])};
    float s = 0.f;
#pragma unroll
    for (int i = 0; i < 8; i++) s += vv[i];
    float mean = warp_sum(s) * (1.f / 256);
    float va = 0.f;
#pragma unroll
    for (int i = 0; i < 8; i++) { vv[i] -= mean; va += vv[i] * vv[i]; }
    float rs = rsqrtf(warp_sum(va) * (1.f / 256) + 1e-5f);
    float4 g0 = ((const float4*)g)[lane * 2], g1 = ((const float4*)g)[lane * 2 + 1];
    float4 b0 = ((const float4*)b)[lane * 2], b1 = ((const float4*)b)[lane * 2 + 1];
    float gg[8] = {g0.x, g0.y, g0.z, g0.w, g1.x, g1.y, g1.z, g1.w};
    float bb[8] = {b0.x, b0.y, b0.z, b0.w, b1.x, b1.y, b1.z, b1.w};
    float out8[8];
#pragma unroll
    for (int i = 0; i < 8; i++) out8[i] = vv[i] * rs * gg[i] + bb[i];
    float4* yr = (float4*)(y + (size_t)row * 256) + lane * 2;
    yr[0] = make_float4(out8[0], out8[1], out8[2], out8[3]);
    yr[1] = make_float4(out8[4], out8[5], out8[6], out8[7]);
}

// ---------------- deformable sampling (f32 value, as R9) ----------------------
__device__ __forceinline__ float fetch_v(const float* __restrict__ vbase, int x, int y)
{
    if (x < 0 || x >= WL || y < 0 || y >= HL) return 0.f;
    return vbase[(size_t)(y * WL + x) * CDIM];
}

__global__ void msda_kernel(const float* __restrict__ value, const float* __restrict__ oa,
                            const float* __restrict__ ref, __half* __restrict__ o)
{
    const int warp = blockIdx.x * (blockDim.x >> 5) + (threadIdx.x >> 5);
    const int lane = threadIdx.x & 31;
    if (warp >= ROWS * HEADS) return;
    const int hd = warp & 7;
    const int bq = warp >> 3;
    const int b  = bq / LQ;

    const float* oarow = oa + (size_t)bq * 128;
    float a0 = oarow[64 + hd * 4 + 0];
    float a1 = oarow[64 + hd * 4 + 1];
    float a2 = oarow[64 + hd * 4 + 2];
    float a3 = oarow[64 + hd * 4 + 3];
    float m  = fmaxf(fmaxf(a0, a1), fmaxf(a2, a3));
    float e0 = expf(a0 - m), e1 = expf(a1 - m), e2 = expf(a2 - m), e3 = expf(a3 - m);
    float inv = 1.f / (e0 + e1 + e2 + e3);
    float w[4] = {e0 * inv, e1 * inv, e2 * inv, e3 * inv};

    const float rx = ref[(size_t)bq * 2 + 0];
    const float ry = ref[(size_t)bq * 2 + 1];
    const float* vbase = value + (size_t)b * LS * CDIM + hd * HDIM + lane;

    float acc = 0.f;
#pragma unroll
    for (int p = 0; p < NPTS; p++) {
        float ox = oarow[hd * 8 + p * 2 + 0];
        float oy = oarow[hd * 8 + p * 2 + 1];
        float X = (rx + ox / (float)WL) * (float)WL - 0.5f;
        float Y = (ry + oy / (float)HL) * (float)HL - 0.5f;
        float x0f = floorf(X), y0f = floorf(Y);
        float lx = X - x0f, ly = Y - y0f;
        int x0 = (int)x0f, y0 = (int)y0f;
        float s00 = fetch_v(vbase, x0,     y0);
        float s10 = fetch_v(vbase, x0 + 1, y0);
        float s01 = fetch_v(vbase, x0,     y0 + 1);
        float s11 = fetch_v(vbase, x0 + 1, y0 + 1);
        float sv  = s00 * (1.f - lx) * (1.f - ly) + s10 * lx * (1.f - ly)
                  + s01 * (1.f - lx) * ly         + s11 * lx * ly;
        acc = fmaf(w[p], sv, acc);
    }
    o[(size_t)bq * CDIM + hd * HDIM + lane] = __float2half_rn(acc);
}

// ---------------- mma.sync fp16 GEMM (128 threads, 4 warps, 64x64 tiles) ------
// C[ROWS, N] = A16 @ Wh^T + bias   (W stored [n][k], K contiguous)
// OUT = 0: f32, 1: fp16.  GELU optional.
// BM=128 BN=128 BK=32, 2-stage cp.async, 2 CTAs/SM.
#define GSTAGE 20480
#define GSMEM  (2 * GSTAGE)

template<bool GELU, int OUT>
__global__ void __launch_bounds__(128, 2) mgemm_kernel(
    const __half* __restrict__ A, const __half* __restrict__ Bh,
    const float* __restrict__ bias,
    float* __restrict__ outF, __half* __restrict__ outH, int ldo)
{
    extern __shared__ __align__(128) char smem[];
    const int tid = threadIdx.x, lane = tid & 31, wid = tid >> 5;
    const int row0 = blockIdx.x * 128, n0 = blockIdx.y * 128;
    const int wm = wid >> 1, wn = wid & 1;
    const uint32_t sbase = smem_u32(smem);

    float acc[4][8][4];
#pragma unroll
    for (int i = 0; i < 4; i++)
#pragma unroll
        for (int j = 0; j < 8; j++)
#pragma unroll
            for (int q = 0; q < 4; q++) acc[i][j][q] = 0.f;

    auto load_stage = [&](int c, int s) {
        const int kk = c * 32;
        const uint32_t st = sbase + s * GSTAGE;
#pragma unroll
        for (int i = 0; i < 4; i++) {
            int g = i * 128 + tid;
            int r = g >> 2, cc = g & 3;
            uint32_t so = (uint32_t)(r * 80 + cc * 16);
            int gr = row0 + r;
            uint32_t sz = (gr < ROWS) ? 16u : 0u;
            cpa16(st + so,         A  + (size_t)gr * 256 + kk + cc * 8, sz);
            cpa16(st + 10240 + so, Bh + (size_t)(n0 + r) * 256 + kk + cc * 8, 16u);
        }
        asm volatile("cp.async.commit_group;" ::: "memory");
    };

    load_stage(0, 0);
    load_stage(1, 1);

#pragma unroll 1
    for (int c = 0; c < 8; c++) {
        if (c < 7) asm volatile("cp.async.wait_group 1;" ::: "memory");
        else       asm volatile("cp.async.wait_group 0;" ::: "memory");
        __syncthreads();

        const uint32_t st = sbase + (c & 1) * GSTAGE;
#pragma unroll
        for (int k16 = 0; k16 < 2; k16++) {
            uint32_t bh[8][2];
            {
                int br = wn * 64 + ((lane >> 4) << 3) + (lane & 7);
                int bc = k16 * 16 + ((lane >> 3) & 1) * 8;
#pragma unroll
                for (int p = 0; p < 4; p++) {
                    uint32_t bd = st + 10240 + (uint32_t)((br + p * 16) * 80 + bc * 2);
                    uint32_t t4[4];
                    ldm_x4(t4, bd);
                    bh[2 * p][0] = t4[0]; bh[2 * p][1] = t4[1];
                    bh[2 * p + 1][0] = t4[2]; bh[2 * p + 1][1] = t4[3];
                }
            }
            int ar = wm * 64 + (lane & 15);
            int ac = k16 * 16 + ((lane >> 4) << 3);
#pragma unroll
            for (int mi = 0; mi < 4; mi++) {
                uint32_t ah[4];
                ldm_x4(ah, st + (uint32_t)((ar + mi * 16) * 80 + ac * 2));
#pragma unroll
                for (int nj = 0; nj < 8; nj++)
                    mma_f16(acc[mi][nj], ah, bh[nj]);
            }
        }
        __syncthreads();
        if (c <= 5) load_stage(c + 2, c & 1);
    }

#pragma unroll
    for (int mi = 0; mi < 4; mi++) {
        int rl = row0 + wm * 64 + mi * 16 + (lane >> 2);
        int rh = rl + 8;
#pragma unroll
        for (int nj = 0; nj < 8; nj++) {
            int col = n0 + wn * 64 + nj * 8 + (lane & 3) * 2;
            float b0 = __ldg(&bias[col]), b1 = __ldg(&bias[col + 1]);
            float v0 = acc[mi][nj][0] + b0, v1 = acc[mi][nj][1] + b1;
            float v2 = acc[mi][nj][2] + b0, v3 = acc[mi][nj][3] + b1;
            if (GELU) {
                v0 = 0.5f * v0 * (1.f + erff(v0 * 0.70710678118654752f));
                v1 = 0.5f * v1 * (1.f + erff(v1 * 0.70710678118654752f));
                v2 = 0.5f * v2 * (1.f + erff(v2 * 0.70710678118654752f));
                v3 = 0.5f * v3 * (1.f + erff(v3 * 0.70710678118654752f));
            }
            if (OUT == 0) {
                if (rl < ROWS) *(float2*)(outF + (size_t)rl * ldo + col) = make_float2(v0, v1);
                if (rh < ROWS) *(float2*)(outF + (size_t)rh * ldo + col) = make_float2(v2, v3);
            } else {
                union { __half h[2]; uint32_t u; } pl, ph;
                pl.h[0] = __float2half_rn(v0); pl.h[1] = __float2half_rn(v1);
                ph.h[0] = __float2half_rn(v2); ph.h[1] = __float2half_rn(v3);
                if (rl < ROWS) *(uint32_t*)(outH + (size_t)rl * ldo + col) = pl.u;
                if (rh < ROWS) *(uint32_t*)(outH + (size_t)rh * ldo + col) = ph.u;
            }
        }
    }
}

// ---------------- launch -------------------------------------------------------
extern "C" void kernel_launch(void* const* d_in, const int* in_sizes, int n_in,
                              void* d_out, int out_size)
{
    const float* tgt       = (const float*)d_in[0];
    const float* query_pos = (const float*)d_in[1];
    const float* refpts    = (const float*)d_in[4];
    const float* src       = (const float*)d_in[6];
    const float* W_dsa = (const float*)d_in[10]; const float* b_dsa = (const float*)d_in[11];
    const float* g_nds = (const float*)d_in[12]; const float* b_nds = (const float*)d_in[13];
    const float* W_off = (const float*)d_in[14]; const float* b_off = (const float*)d_in[15];
    const float* W_att = (const float*)d_in[16]; const float* b_att = (const float*)d_in[17];
    const float* W_val = (const float*)d_in[18]; const float* b_val = (const float*)d_in[19];
    const float* W_out = (const float*)d_in[20]; const float* b_out = (const float*)d_in[21];
    const float* W_csa = (const float*)d_in[22]; const float* b_csa = (const float*)d_in[23];
    const float* g_n1  = (const float*)d_in[24]; const float* b_n1  = (const float*)d_in[25];
    const float* W_ff  = (const float*)d_in[26]; const float* b_ff  = (const float*)d_in[27];
    const float* g_n3  = (const float*)d_in[28]; const float* b_n3  = (const float*)d_in[29];
    float* out = (float*)d_out;

    float *buf0, *buf2, *oa, *boa, *bcomb;
    __half *sf16, *q16, *h16b, *wth, *woah;
    cudaGetSymbolAddress((void**)&buf0,  g_buf0);
    cudaGetSymbolAddress((void**)&buf2,  g_buf2);
    cudaGetSymbolAddress((void**)&oa,    g_oa);
    cudaGetSymbolAddress((void**)&boa,   g_boa);
    cudaGetSymbolAddress((void**)&bcomb, g_bcomb);
    cudaGetSymbolAddress((void**)&sf16,  g_sf16);
    cudaGetSymbolAddress((void**)&q16,   g_q16);
    cudaGetSymbolAddress((void**)&h16b,  g_h16b);
    cudaGetSymbolAddress((void**)&wth,   g_wt_h16);
    cudaGetSymbolAddress((void**)&woah,  g_woa_h16);

    cudaFuncSetAttribute((const void*)mgemm_kernel<false, 0>,
                         cudaFuncAttributeMaxDynamicSharedMemorySize, GSMEM);
    cudaFuncSetAttribute((const void*)mgemm_kernel<false, 1>,
                         cudaFuncAttributeMaxDynamicSharedMemorySize, GSMEM);
    cudaFuncSetAttribute((const void*)mgemm_kernel<true, 1>,
                         cudaFuncAttributeMaxDynamicSharedMemorySize, GSMEM);

    const int MT  = (ROWS + 127) / 128;       // 235 row tiles
    const dim3 gFull(MT, 2);                  // N = 256
    const dim3 gOA  (MT, 1);                  // N = 128 (96 padded)
    const int EW8 = (ROWS * CDIM / 8 + 255) / 256;
    const int LNB = ROWS / 8;

    // 1) combined weight + prep
    comb_kernel<<<256, 256>>>(W_out, W_csa, b_out, b_csa);
    prep_kernel<<<(PREP_TOT + 255) / 256, 256>>>(W_dsa, W_val, W_ff,
                                                 W_off, W_att, b_off, b_att);
    // 2) src -> sf16 ; tgt+query_pos -> q16
    prep_act_kernel<<<EW8, 256>>>(src, tgt, query_pos, sf16, q16);
    // 3) dsa GEMM -> h16b (fp16)
    mgemm_kernel<false, 1><<<gFull, 128, GSMEM>>>(
        sf16, wth + 0 * 65536, b_dsa, nullptr, h16b, 256);
    // 4) LN(nds) fp16->fp16
    ln_h_warp<<<LNB, 256>>>(h16b, g_nds, b_nds, sf16);
    // 5) value GEMM -> buf0 (f32)
    mgemm_kernel<false, 0><<<gFull, 128, GSMEM>>>(
        sf16, wth + 1 * 65536, b_val, buf0, nullptr, 256);
    // 6) offsets+attention GEMM (reads q16) -> oa
    mgemm_kernel<false, 0><<<gOA, 128, GSMEM>>>(
        q16, woah, boa, oa, nullptr, 128);
    // 7) deformable sampling (f32 value) -> sf16
    msda_kernel<<<(ROWS * HEADS + 7) / 8, 256>>>(buf0, oa, refpts, sf16);
    // 8) combined out+csa GEMM -> h16b (fp16)
    mgemm_kernel<false, 1><<<gFull, 128, GSMEM>>>(
        sf16, wth + 2 * 65536, bcomb, nullptr, h16b, 256);
    // 9) t = LN(tgt + h16b) -> buf2 (f32) + sf16
    addln_h2_warp<<<LNB, 256>>>(tgt, h16b, g_n1, b_n1, buf2, sf16);
    // 10) ff = gelu(t @ W_ff + b_ff) -> h16b (fp16)
    mgemm_kernel<true, 1><<<gFull, 128, GSMEM>>>(
        sf16, wth + 3 * 65536, b_ff, nullptr, h16b, 256);
    // 11) out = LN(buf2 + h16b)
    addln_h_warp<<<LNB, 256>>>(buf2, h16b, g_n3, b_n3, out);
}

// round 15
// speedup vs baseline: 1.1886x; 1.0583x over previous
#include <cuda_runtime.h>
#include <cuda_fp16.h>
#include <cstdint>
#include <math.h>

// ---------------- problem constants ------------------------------------------
#define BATCH   2
#define LQ      15000
#define ROWS    (BATCH * LQ)      // 30000
#define CDIM    256
#define HEADS   8
#define HDIM    32
#define NPTS    4
#define HL      100
#define WL      150
#define LS      (HL * WL)

// ---------------- scratch ----------------------------------------------------
__device__ __align__(16) float   g_buf0[ROWS * CDIM];          // f32 value tensor
__device__ __align__(16) float   g_oa  [ROWS * 96];
__device__ __align__(16) __half  g_sf16[ROWS * CDIM];          // fp16 activations
__device__ __align__(16) __half  g_q16 [ROWS * CDIM];          // fp16 q = tgt+query_pos
__device__ __align__(16) __half  g_h16b[ROWS * CDIM];          // fp16 gemm outputs
__device__ __align__(16) __half  g_wt_h16[4 * 65536];          // [w][n][k]: dsa,val,comb,ff
__device__ __align__(16) __half  g_woa_h16[96 * 256];
__device__ __align__(16) float   g_boa[96];
__device__ __align__(16) float   g_bcomb[256];

// ---------------- ptx helpers ------------------------------------------------
__device__ __forceinline__ uint32_t smem_u32(const void* p) {
    uint32_t a;
    asm("{ .reg .u64 t; cvta.to.shared.u64 t, %1; cvt.u32.u64 %0, t; }" : "=r"(a) : "l"(p));
    return a;
}
__device__ __forceinline__ void cpa16(uint32_t dst, const void* src, uint32_t sz) {
    asm volatile("cp.async.cg.shared.global [%0], [%1], 16, %2;"
                 :: "r"(dst), "l"(src), "r"(sz));
}
__device__ __forceinline__ void ldm_x4(uint32_t* r, uint32_t addr) {
    asm volatile("ldmatrix.sync.aligned.m8n8.x4.shared.b16 {%0,%1,%2,%3}, [%4];"
                 : "=r"(r[0]), "=r"(r[1]), "=r"(r[2]), "=r"(r[3]) : "r"(addr));
}
__device__ __forceinline__ void mma_f16(float* d, const uint32_t* a, const uint32_t* b) {
    asm volatile("mma.sync.aligned.m16n8k16.row.col.f32.f16.f16.f32 "
        "{%0,%1,%2,%3}, {%4,%5,%6,%7}, {%8,%9}, {%0,%1,%2,%3};"
        : "+f"(d[0]), "+f"(d[1]), "+f"(d[2]), "+f"(d[3])
        : "r"(a[0]), "r"(a[1]), "r"(a[2]), "r"(a[3]), "r"(b[0]), "r"(b[1]));
}

// ---------------- weight prep (merged comb): transpose + fp16 -----------------
// index layout:
//   [0, 262144)            wt matrices (w = idx>>16): dsa, val, comb(dot), ff
//   [262144, 286720)       woa (96 x 256)
//   [286720, 286816)       boa (96)
//   [286816, 287072)       bcomb (256)
#define PREP_WT   262144
#define PREP_WOA  (PREP_WT + 96 * 256)
#define PREP_BOA  (PREP_WOA + 96)
#define PREP_TOT  (PREP_BOA + 256)
__global__ void prep_kernel(const float* __restrict__ Wd, const float* __restrict__ Wv,
                            const float* __restrict__ Wo, const float* __restrict__ Wc,
                            const float* __restrict__ Wf,
                            const float* __restrict__ bo, const float* __restrict__ bc,
                            const float* __restrict__ Woff, const float* __restrict__ Watt,
                            const float* __restrict__ boff, const float* __restrict__ batt)
{
    int idx = blockIdx.x * 256 + threadIdx.x;
    if (idx < PREP_WT) {
        int w = idx >> 16, e = idx & 65535;
        if (w == 2) {
            // comb = W_out @ W_csa ; lane-map n contiguous for coalesced Wc reads
            int n = e & 255, k = e >> 8;
            float s = 0.f;
#pragma unroll 8
            for (int j = 0; j < 256; j++)
                s = fmaf(Wo[k * 256 + j], Wc[j * 256 + n], s);
            g_wt_h16[2 * 65536 + n * 256 + k] = __float2half_rn(s);
        } else {
            int n = e >> 8, k = e & 255;
            float v;
            if (w == 0)      v = Wd[k * 256 + n];
            else if (w == 1) v = Wv[k * 256 + n];
            else             v = Wf[k * 256 + n];
            g_wt_h16[w * 65536 + n * 256 + k] = __float2half_rn(v);
        }
    } else if (idx < PREP_WOA) {
        int e = idx - PREP_WT, n = e >> 8, k = e & 255;
        float v = (n < 64) ? Woff[k * 64 + n] : Watt[k * 32 + (n - 64)];
        g_woa_h16[n * 256 + k] = __float2half_rn(v);
    } else if (idx < PREP_BOA) {
        int j = idx - PREP_WOA;
        g_boa[j] = (j < 64) ? boff[j] : batt[j - 64];
    } else if (idx < PREP_TOT) {
        int n = idx - PREP_BOA;
        float s = 0.f;
#pragma unroll 8
        for (int j = 0; j < 256; j++) s = fmaf(bo[j], Wc[j * 256 + n], s);
        g_bcomb[n] = s + bc[n];
    }
}

// ---------------- activation prep: src->fp16, tgt+qp->fp16 --------------------
__global__ void prep_act_kernel(const float* __restrict__ src, const float* __restrict__ tgt,
                                const float* __restrict__ qp,
                                __half* __restrict__ s16, __half* __restrict__ q16)
{
    int base = (blockIdx.x * 256 + threadIdx.x) * 8;
    if (base >= ROWS * CDIM) return;
    float4 s0 = *(const float4*)(src + base), s1 = *(const float4*)(src + base + 4);
    union { __half h[8]; uint4 u; } p;
    p.h[0] = __float2half_rn(s0.x); p.h[1] = __float2half_rn(s0.y);
    p.h[2] = __float2half_rn(s0.z); p.h[3] = __float2half_rn(s0.w);
    p.h[4] = __float2half_rn(s1.x); p.h[5] = __float2half_rn(s1.y);
    p.h[6] = __float2half_rn(s1.z); p.h[7] = __float2half_rn(s1.w);
    *(uint4*)(s16 + base) = p.u;
    float4 a0 = *(const float4*)(tgt + base), a1 = *(const float4*)(tgt + base + 4);
    float4 b0 = *(const float4*)(qp + base),  b1 = *(const float4*)(qp + base + 4);
    p.h[0] = __float2half_rn(a0.x + b0.x); p.h[1] = __float2half_rn(a0.y + b0.y);
    p.h[2] = __float2half_rn(a0.z + b0.z); p.h[3] = __float2half_rn(a0.w + b0.w);
    p.h[4] = __float2half_rn(a1.x + b1.x); p.h[5] = __float2half_rn(a1.y + b1.y);
    p.h[6] = __float2half_rn(a1.z + b1.z); p.h[7] = __float2half_rn(a1.w + b1.w);
    *(uint4*)(q16 + base) = p.u;
}

// ---------------- warp-per-row layernorm kernels ------------------------------
__device__ __forceinline__ float warp_sum(float v)
{
#pragma unroll
    for (int o = 16; o > 0; o >>= 1) v += __shfl_xor_sync(0xffffffffu, v, o);
    return v;
}

// fp16 in -> LN -> fp16 out
__global__ void ln_h_warp(const __half* __restrict__ x, const float* __restrict__ g,
                          const float* __restrict__ b, __half* __restrict__ o)
{
    const int w = threadIdx.x >> 5, lane = threadIdx.x & 31;
    const int row = blockIdx.x * 8 + w;
    union { __half h[8]; uint4 u; } in;
    in.u = *(const uint4*)(x + (size_t)row * 256 + lane * 8);
    float vv[8];
#pragma unroll
    for (int i = 0; i < 8; i++) vv[i] = __half2float(in.h[i]);
    float s = 0.f;
#pragma unroll
    for (int i = 0; i < 8; i++) s += vv[i];
    float mean = warp_sum(s) * (1.f / 256);
    float va = 0.f;
#pragma unroll
    for (int i = 0; i < 8; i++) { vv[i] -= mean; va += vv[i] * vv[i]; }
    float rs = rsqrtf(warp_sum(va) * (1.f / 256) + 1e-5f);
    float4 g0 = ((const float4*)g)[lane * 2], g1 = ((const float4*)g)[lane * 2 + 1];
    float4 b0 = ((const float4*)b)[lane * 2], b1 = ((const float4*)b)[lane * 2 + 1];
    float gg[8] = {g0.x, g0.y, g0.z, g0.w, g1.x, g1.y, g1.z, g1.w};
    float bb[8] = {b0.x, b0.y, b0.z, b0.w, b1.x, b1.y, b1.z, b1.w};
    union { __half h[8]; uint4 u; } p;
#pragma unroll
    for (int i = 0; i < 8; i++) p.h[i] = __float2half_rn(vv[i] * rs * gg[i] + bb[i]);
    *(uint4*)(o + (size_t)row * 256 + lane * 8) = p.u;
}

// LN(a_f32 + c_fp16) -> fp16 o only
__global__ void addln_hh_warp(const float* __restrict__ a, const __half* __restrict__ c,
                              const float* __restrict__ g, const float* __restrict__ b,
                              __half* __restrict__ o)
{
    const int w = threadIdx.x >> 5, lane = threadIdx.x & 31;
    const int row = blockIdx.x * 8 + w;
    const float4* ar = (const float4*)(a + (size_t)row * 256) + lane * 2;
    float4 a0 = ar[0], a1 = ar[1];
    union { __half h[8]; uint4 u; } ch;
    ch.u = *(const uint4*)(c + (size_t)row * 256 + lane * 8);
    float vv[8] = {a0.x + __half2float(ch.h[0]), a0.y + __half2float(ch.h[1]),
                   a0.z + __half2float(ch.h[2]), a0.w + __half2float(ch.h[3]),
                   a1.x + __half2float(ch.h[4]), a1.y + __half2float(ch.h[5]),
                   a1.z + __half2float(ch.h[6]), a1.w + __half2float(ch.h[7])};
    float s = 0.f;
#pragma unroll
    for (int i = 0; i < 8; i++) s += vv[i];
    float mean = warp_sum(s) * (1.f / 256);
    float va = 0.f;
#pragma unroll
    for (int i = 0; i < 8; i++) { vv[i] -= mean; va += vv[i] * vv[i]; }
    float rs = rsqrtf(warp_sum(va) * (1.f / 256) + 1e-5f);
    float4 g0 = ((const float4*)g)[lane * 2], g1 = ((const float4*)g)[lane * 2 + 1];
    float4 b0 = ((const float4*)b)[lane * 2], b1 = ((const float4*)b)[lane * 2 + 1];
    float gg[8] = {g0.x, g0.y, g0.z, g0.w, g1.x, g1.y, g1.z, g1.w};
    float bb[8] = {b0.x, b0.y, b0.z, b0.w, b1.x, b1.y, b1.z, b1.w};
    union { __half h[8]; uint4 u; } p;
#pragma unroll
    for (int i = 0; i < 8; i++) p.h[i] = __float2half_rn(vv[i] * rs * gg[i] + bb[i]);
    *(uint4*)(o + (size_t)row * 256 + lane * 8) = p.u;
}

// out = LN(a_fp16 + c_fp16) (f32)
__global__ void addln_2h_warp(const __half* __restrict__ a, const __half* __restrict__ c,
                              const float* __restrict__ g, const float* __restrict__ b,
                              float* __restrict__ y)
{
    const int w = threadIdx.x >> 5, lane = threadIdx.x & 31;
    const int row = blockIdx.x * 8 + w;
    union { __half h[8]; uint4 u; } ah, ch;
    ah.u = *(const uint4*)(a + (size_t)row * 256 + lane * 8);
    ch.u = *(const uint4*)(c + (size_t)row * 256 + lane * 8);
    float vv[8];
#pragma unroll
    for (int i = 0; i < 8; i++)
        vv[i] = __half2float(ah.h[i]) + __half2float(ch.h[i]);
    float s = 0.f;
#pragma unroll
    for (int i = 0; i < 8; i++) s += vv[i];
    float mean = warp_sum(s) * (1.f / 256);
    float va = 0.f;
#pragma unroll
    for (int i = 0; i < 8; i++) { vv[i] -= mean; va += vv[i] * vv[i]; }
    float rs = rsqrtf(warp_sum(va) * (1.f / 256) + 1e-5f);
    float4 g0 = ((const float4*)g)[lane * 2], g1 = ((const float4*)g)[lane * 2 + 1];
    float4 b0 = ((const float4*)b)[lane * 2], b1 = ((const float4*)b)[lane * 2 + 1];
    float gg[8] = {g0.x, g0.y, g0.z, g0.w, g1.x, g1.y, g1.z, g1.w};
    float bb[8] = {b0.x, b0.y, b0.z, b0.w, b1.x, b1.y, b1.z, b1.w};
    float out8[8];
#pragma unroll
    for (int i = 0; i < 8; i++) out8[i] = vv[i] * rs * gg[i] + bb[i];
    float4* yr = (float4*)(y + (size_t)row * 256) + lane * 2;
    yr[0] = make_float4(out8[0], out8[1], out8[2], out8[3]);
    yr[1] = make_float4(out8[4], out8[5], out8[6], out8[7]);
}

// ---------------- deformable sampling (f32 value, oa stride 96) ---------------
__device__ __forceinline__ float fetch_v(const float* __restrict__ vbase, int x, int y)
{
    if (x < 0 || x >= WL || y < 0 || y >= HL) return 0.f;
    return vbase[(size_t)(y * WL + x) * CDIM];
}

__global__ void msda_kernel(const float* __restrict__ value, const float* __restrict__ oa,
                            const float* __restrict__ ref, __half* __restrict__ o)
{
    const int warp = blockIdx.x * (blockDim.x >> 5) + (threadIdx.x >> 5);
    const int lane = threadIdx.x & 31;
    if (warp >= ROWS * HEADS) return;
    const int hd = warp & 7;
    const int bq = warp >> 3;
    const int b  = bq / LQ;

    const float* oarow = oa + (size_t)bq * 96;
    float a0 = oarow[64 + hd * 4 + 0];
    float a1 = oarow[64 + hd * 4 + 1];
    float a2 = oarow[64 + hd * 4 + 2];
    float a3 = oarow[64 + hd * 4 + 3];
    float m  = fmaxf(fmaxf(a0, a1), fmaxf(a2, a3));
    float e0 = expf(a0 - m), e1 = expf(a1 - m), e2 = expf(a2 - m), e3 = expf(a3 - m);
    float inv = 1.f / (e0 + e1 + e2 + e3);
    float w[4] = {e0 * inv, e1 * inv, e2 * inv, e3 * inv};

    const float rx = ref[(size_t)bq * 2 + 0];
    const float ry = ref[(size_t)bq * 2 + 1];
    const float* vbase = value + (size_t)b * LS * CDIM + hd * HDIM + lane;

    float acc = 0.f;
#pragma unroll
    for (int p = 0; p < NPTS; p++) {
        float ox = oarow[hd * 8 + p * 2 + 0];
        float oy = oarow[hd * 8 + p * 2 + 1];
        float X = (rx + ox / (float)WL) * (float)WL - 0.5f;
        float Y = (ry + oy / (float)HL) * (float)HL - 0.5f;
        float x0f = floorf(X), y0f = floorf(Y);
        float lx = X - x0f, ly = Y - y0f;
        int x0 = (int)x0f, y0 = (int)y0f;
        float s00 = fetch_v(vbase, x0,     y0);
        float s10 = fetch_v(vbase, x0 + 1, y0);
        float s01 = fetch_v(vbase, x0,     y0 + 1);
        float s11 = fetch_v(vbase, x0 + 1, y0 + 1);
        float sv  = s00 * (1.f - lx) * (1.f - ly) + s10 * lx * (1.f - ly)
                  + s01 * (1.f - lx) * ly         + s11 * lx * ly;
        acc = fmaf(w[p], sv, acc);
    }
    o[(size_t)bq * CDIM + hd * HDIM + lane] = __float2half_rn(acc);
}

// ---------------- mma.sync fp16 GEMM (128 threads, 4 warps, 64x64 tiles) ------
// C[ROWS, 256 tile-col n0] = A16 @ Wh^T + bias.  OUT = 0: f32, 1: fp16.
#define GSTAGE 20480
#define GSMEM  (2 * GSTAGE)

template<bool GELU, int OUT>
__global__ void __launch_bounds__(128, 2) mgemm_kernel(
    const __half* __restrict__ A, const __half* __restrict__ Bh,
    const float* __restrict__ bias,
    float* __restrict__ outF, __half* __restrict__ outH, int ldo)
{
    extern __shared__ __align__(128) char smem[];
    const int tid = threadIdx.x, lane = tid & 31, wid = tid >> 5;
    const int row0 = blockIdx.x * 128, n0 = blockIdx.y * 128;
    const int wm = wid >> 1, wn = wid & 1;
    const uint32_t sbase = smem_u32(smem);

    float acc[4][8][4];
#pragma unroll
    for (int i = 0; i < 4; i++)
#pragma unroll
        for (int j = 0; j < 8; j++)
#pragma unroll
            for (int q = 0; q < 4; q++) acc[i][j][q] = 0.f;

    auto load_stage = [&](int c, int s) {
        const int kk = c * 32;
        const uint32_t st = sbase + s * GSTAGE;
#pragma unroll
        for (int i = 0; i < 4; i++) {
            int g = i * 128 + tid;
            int r = g >> 2, cc = g & 3;
            uint32_t so = (uint32_t)(r * 80 + cc * 16);
            int gr = row0 + r;
            uint32_t sz = (gr < ROWS) ? 16u : 0u;
            cpa16(st + so,         A  + (size_t)gr * 256 + kk + cc * 8, sz);
            cpa16(st + 10240 + so, Bh + (size_t)(n0 + r) * 256 + kk + cc * 8, 16u);
        }
        asm volatile("cp.async.commit_group;" ::: "memory");
    };

    load_stage(0, 0);
    load_stage(1, 1);

#pragma unroll 1
    for (int c = 0; c < 8; c++) {
        if (c < 7) asm volatile("cp.async.wait_group 1;" ::: "memory");
        else       asm volatile("cp.async.wait_group 0;" ::: "memory");
        __syncthreads();

        const uint32_t st = sbase + (c & 1) * GSTAGE;
#pragma unroll
        for (int k16 = 0; k16 < 2; k16++) {
            uint32_t bh[8][2];
            {
                int br = wn * 64 + ((lane >> 4) << 3) + (lane & 7);
                int bc = k16 * 16 + ((lane >> 3) & 1) * 8;
#pragma unroll
                for (int p = 0; p < 4; p++) {
                    uint32_t bd = st + 10240 + (uint32_t)((br + p * 16) * 80 + bc * 2);
                    uint32_t t4[4];
                    ldm_x4(t4, bd);
                    bh[2 * p][0] = t4[0]; bh[2 * p][1] = t4[1];
                    bh[2 * p + 1][0] = t4[2]; bh[2 * p + 1][1] = t4[3];
                }
            }
            int ar = wm * 64 + (lane & 15);
            int ac = k16 * 16 + ((lane >> 4) << 3);
#pragma unroll
            for (int mi = 0; mi < 4; mi++) {
                uint32_t ah[4];
                ldm_x4(ah, st + (uint32_t)((ar + mi * 16) * 80 + ac * 2));
#pragma unroll
                for (int nj = 0; nj < 8; nj++)
                    mma_f16(acc[mi][nj], ah, bh[nj]);
            }
        }
        __syncthreads();
        if (c <= 5) load_stage(c + 2, c & 1);
    }

#pragma unroll
    for (int mi = 0; mi < 4; mi++) {
        int rl = row0 + wm * 64 + mi * 16 + (lane >> 2);
        int rh = rl + 8;
#pragma unroll
        for (int nj = 0; nj < 8; nj++) {
            int col = n0 + wn * 64 + nj * 8 + (lane & 3) * 2;
            float b0 = __ldg(&bias[col]), b1 = __ldg(&bias[col + 1]);
            float v0 = acc[mi][nj][0] + b0, v1 = acc[mi][nj][1] + b1;
            float v2 = acc[mi][nj][2] + b0, v3 = acc[mi][nj][3] + b1;
            if (GELU) {
                v0 = 0.5f * v0 * (1.f + erff(v0 * 0.70710678118654752f));
                v1 = 0.5f * v1 * (1.f + erff(v1 * 0.70710678118654752f));
                v2 = 0.5f * v2 * (1.f + erff(v2 * 0.70710678118654752f));
                v3 = 0.5f * v3 * (1.f + erff(v3 * 0.70710678118654752f));
            }
            if (OUT == 0) {
                if (rl < ROWS) *(float2*)(outF + (size_t)rl * ldo + col) = make_float2(v0, v1);
                if (rh < ROWS) *(float2*)(outF + (size_t)rh * ldo + col) = make_float2(v2, v3);
            } else {
                union { __half h[2]; uint32_t u; } pl, ph;
                pl.h[0] = __float2half_rn(v0); pl.h[1] = __float2half_rn(v1);
                ph.h[0] = __float2half_rn(v2); ph.h[1] = __float2half_rn(v3);
                if (rl < ROWS) *(uint32_t*)(outH + (size_t)rl * ldo + col) = pl.u;
                if (rh < ROWS) *(uint32_t*)(outH + (size_t)rh * ldo + col) = ph.u;
            }
        }
    }
}

// ---------------- oa GEMM: BM=128 BN=96 (no padding), 4 warps, 2 CTAs/SM ------
#define OSTAGE (10240 + 7680)
#define OSMEM  (2 * OSTAGE)

__global__ void __launch_bounds__(128, 2) oagemm_kernel(
    const __half* __restrict__ A, const __half* __restrict__ Bh,
    const float* __restrict__ bias, float* __restrict__ outF)
{
    extern __shared__ __align__(128) char smem[];
    const int tid = threadIdx.x, lane = tid & 31, wid = tid >> 5;
    const int row0 = blockIdx.x * 128;
    const int wm = wid >> 1, wn = wid & 1;           // 2x2 grid, warp tile 64x48
    const uint32_t sbase = smem_u32(smem);

    float acc[4][6][4];
#pragma unroll
    for (int i = 0; i < 4; i++)
#pragma unroll
        for (int j = 0; j < 6; j++)
#pragma unroll
            for (int q = 0; q < 4; q++) acc[i][j][q] = 0.f;

    auto load_stage = [&](int c, int s) {
        const int kk = c * 32;
        const uint32_t st = sbase + s * OSTAGE;
#pragma unroll
        for (int i = 0; i < 4; i++) {                // A: 512 granules
            int g = i * 128 + tid;
            int r = g >> 2, cc = g & 3;
            int gr = row0 + r;
            uint32_t sz = (gr < ROWS) ? 16u : 0u;
            cpa16(st + (uint32_t)(r * 80 + cc * 16),
                  A + (size_t)gr * 256 + kk + cc * 8, sz);
        }
#pragma unroll
        for (int i = 0; i < 3; i++) {                // B: 384 granules (96 rows)
            int g = i * 128 + tid;
            int r = g >> 2, cc = g & 3;
            cpa16(st + 10240 + (uint32_t)(r * 80 + cc * 16),
                  Bh + (size_t)r * 256 + kk + cc * 8, 16u);
        }
        asm volatile("cp.async.commit_group;" ::: "memory");
    };

    load_stage(0, 0);
    load_stage(1, 1);

#pragma unroll 1
    for (int c = 0; c < 8; c++) {
        if (c < 7) asm volatile("cp.async.wait_group 1;" ::: "memory");
        else       asm volatile("cp.async.wait_group 0;" ::: "memory");
        __syncthreads();

        const uint32_t st = sbase + (c & 1) * OSTAGE;
#pragma unroll
        for (int k16 = 0; k16 < 2; k16++) {
            uint32_t bh[6][2];
            {
                int br = wn * 48 + ((lane >> 4) << 3) + (lane & 7);
                int bc = k16 * 16 + ((lane >> 3) & 1) * 8;
#pragma unroll
                for (int p = 0; p < 3; p++) {
                    uint32_t bd = st + 10240 + (uint32_t)((br + p * 16) * 80 + bc * 2);
                    uint32_t t4[4];
                    ldm_x4(t4, bd);
                    bh[2 * p][0] = t4[0]; bh[2 * p][1] = t4[1];
                    bh[2 * p + 1][0] = t4[2]; bh[2 * p + 1][1] = t4[3];
                }
            }
            int ar = wm * 64 + (lane & 15);
            int ac = k16 * 16 + ((lane >> 4) << 3);
#pragma unroll
            for (int mi = 0; mi < 4; mi++) {
                uint32_t ah[4];
                ldm_x4(ah, st + (uint32_t)((ar + mi * 16) * 80 + ac * 2));
#pragma unroll
                for (int nj = 0; nj < 6; nj++)
                    mma_f16(acc[mi][nj], ah, bh[nj]);
            }
        }
        __syncthreads();
        if (c <= 5) load_stage(c + 2, c & 1);
    }

#pragma unroll
    for (int mi = 0; mi < 4; mi++) {
        int rl = row0 + wm * 64 + mi * 16 + (lane >> 2);
        int rh = rl + 8;
#pragma unroll
        for (int nj = 0; nj < 6; nj++) {
            int col = wn * 48 + nj * 8 + (lane & 3) * 2;
            float b0 = __ldg(&bias[col]), b1 = __ldg(&bias[col + 1]);
            if (rl < ROWS) *(float2*)(outF + (size_t)rl * 96 + col) =
                make_float2(acc[mi][nj][0] + b0, acc[mi][nj][1] + b1);
            if (rh < ROWS) *(float2*)(outF + (size_t)rh * 96 + col) =
                make_float2(acc[mi][nj][2] + b0, acc[mi][nj][3] + b1);
        }
    }
}

// ---------------- launch -------------------------------------------------------
extern "C" void kernel_launch(void* const* d_in, const int* in_sizes, int n_in,
                              void* d_out, int out_size)
{
    const float* tgt       = (const float*)d_in[0];
    const float* query_pos = (const float*)d_in[1];
    const float* refpts    = (const float*)d_in[4];
    const float* src       = (const float*)d_in[6];
    const float* W_dsa = (const float*)d_in[10]; const float* b_dsa = (const float*)d_in[11];
    const float* g_nds = (const float*)d_in[12]; const float* b_nds = (const float*)d_in[13];
    const float* W_off = (const float*)d_in[14]; const float* b_off = (const float*)d_in[15];
    const float* W_att = (const float*)d_in[16]; const float* b_att = (const float*)d_in[17];
    const float* W_val = (const float*)d_in[18]; const float* b_val = (const float*)d_in[19];
    const float* W_out = (const float*)d_in[20]; const float* b_out = (const float*)d_in[21];
    const float* W_csa = (const float*)d_in[22]; const float* b_csa = (const float*)d_in[23];
    const float* g_n1  = (const float*)d_in[24]; const float* b_n1  = (const float*)d_in[25];
    const float* W_ff  = (const float*)d_in[26]; const float* b_ff  = (const float*)d_in[27];
    const float* g_n3  = (const float*)d_in[28]; const float* b_n3  = (const float*)d_in[29];
    float* out = (float*)d_out;

    float *buf0, *oa, *boa, *bcomb;
    __half *sf16, *q16, *h16b, *wth, *woah;
    cudaGetSymbolAddress((void**)&buf0,  g_buf0);
    cudaGetSymbolAddress((void**)&oa,    g_oa);
    cudaGetSymbolAddress((void**)&boa,   g_boa);
    cudaGetSymbolAddress((void**)&bcomb, g_bcomb);
    cudaGetSymbolAddress((void**)&sf16,  g_sf16);
    cudaGetSymbolAddress((void**)&q16,   g_q16);
    cudaGetSymbolAddress((void**)&h16b,  g_h16b);
    cudaGetSymbolAddress((void**)&wth,   g_wt_h16);
    cudaGetSymbolAddress((void**)&woah,  g_woa_h16);

    cudaFuncSetAttribute((const void*)mgemm_kernel<false, 0>,
                         cudaFuncAttributeMaxDynamicSharedMemorySize, GSMEM);
    cudaFuncSetAttribute((const void*)mgemm_kernel<false, 1>,
                         cudaFuncAttributeMaxDynamicSharedMemorySize, GSMEM);
    cudaFuncSetAttribute((const void*)mgemm_kernel<true, 1>,
                         cudaFuncAttributeMaxDynamicSharedMemorySize, GSMEM);
    cudaFuncSetAttribute((const void*)oagemm_kernel,
                         cudaFuncAttributeMaxDynamicSharedMemorySize, OSMEM);

    const int MT  = (ROWS + 127) / 128;       // 235 row tiles
    const dim3 gFull(MT, 2);                  // N = 256
    const int EW8 = (ROWS * CDIM / 8 + 255) / 256;
    const int LNB = ROWS / 8;

    // 1) weight prep (incl. comb fold)
    prep_kernel<<<(PREP_TOT + 255) / 256, 256>>>(W_dsa, W_val, W_out, W_csa, W_ff,
                                                 b_out, b_csa, W_off, W_att, b_off, b_att);
    // 2) src -> sf16 ; tgt+query_pos -> q16
    prep_act_kernel<<<EW8, 256>>>(src, tgt, query_pos, sf16, q16);
    // 3) dsa GEMM -> h16b (fp16)
    mgemm_kernel<false, 1><<<gFull, 128, GSMEM>>>(
        sf16, wth + 0 * 65536, b_dsa, nullptr, h16b, 256);
    // 4) LN(nds) fp16->fp16
    ln_h_warp<<<LNB, 256>>>(h16b, g_nds, b_nds, sf16);
    // 5) value GEMM -> buf0 (f32)
    mgemm_kernel<false, 0><<<gFull, 128, GSMEM>>>(
        sf16, wth + 1 * 65536, b_val, buf0, nullptr, 256);
    // 6) offsets+attention GEMM (N=96, reads q16) -> oa
    oagemm_kernel<<<MT, 128, OSMEM>>>(q16, woah, boa, oa);
    // 7) deformable sampling -> sf16
    msda_kernel<<<(ROWS * HEADS + 7) / 8, 256>>>(buf0, oa, refpts, sf16);
    // 8) combined out+csa GEMM -> h16b (fp16)
    mgemm_kernel<false, 1><<<gFull, 128, GSMEM>>>(
        sf16, wth + 2 * 65536, bcomb, nullptr, h16b, 256);
    // 9) t = LN(tgt + h16b) -> sf16 (fp16 only)
    addln_hh_warp<<<LNB, 256>>>(tgt, h16b, g_n1, b_n1, sf16);
    // 10) ff = gelu(t @ W_ff + b_ff) -> h16b (fp16)
    mgemm_kernel<true, 1><<<gFull, 128, GSMEM>>>(
        sf16, wth + 3 * 65536, b_ff, nullptr, h16b, 256);
    // 11) out = LN(sf16 + h16b)
    addln_2h_warp<<<LNB, 256>>>(sf16, h16b, g_n3, b_n3, out);
}